// round 9
// baseline (speedup 1.0000x reference)
#include <cuda_runtime.h>
#include <cuda_fp16.h>
#include <math.h>
#include <stdint.h>

// Problem shape (fixed): B=16384 rows, D=1024, grid 32x32 -> N=1024 codes
#define BROWS 16384
#define DIM   1024
#define NCODE 1024

// ---------------- scratch (__device__ globals; allocation-free rule) -------
__device__ float g_logits[(size_t)BROWS * NCODE];    // 64MB
__device__ float g_wsq[NCODE];
__device__ int8_t g_xa0[(size_t)BROWS * DIM];        // x limb 0 (scale 2^-4)
__device__ int8_t g_xa1[(size_t)BROWS * DIM];        // x limb 1 (scale 2^-12)
__device__ int8_t g_wb0[(size_t)NCODE * DIM];        // w limb 0 (scale 2^-8)
__device__ int8_t g_wb1[(size_t)NCODE * DIM];        // w limb 1 (scale 2^-16)
__device__ __half g_wthi[(size_t)DIM * NCODE];       // W^T fp16 (GEMM2 B)
__device__ __half g_phi[(size_t)BROWS * NCODE];      // P fp16

// ---------------- PTX helpers ----------------------------------------------
__device__ __forceinline__ uint32_t s2u(const void* p) {
    uint32_t a;
    asm("{ .reg .u64 t; cvta.to.shared.u64 t, %1; cvt.u32.u64 %0, t; }" : "=r"(a) : "l"(p));
    return a;
}
__device__ __forceinline__ uint32_t swz128(uint32_t o) { return o ^ ((o >> 3) & 0x70); }

__device__ __forceinline__ void cpa16(uint32_t dst, const void* src) {
    asm volatile("cp.async.cg.shared.global [%0], [%1], 16;" :: "r"(dst), "l"(src));
}
#define CP_COMMIT() asm volatile("cp.async.commit_group;")
#define CP_WAIT(n)  asm volatile("cp.async.wait_group %0;" :: "n"(n))

__device__ __forceinline__ void ldsm_x4(uint32_t* r, uint32_t addr) {
    asm volatile("ldmatrix.sync.aligned.m8n8.x4.shared.b16 {%0,%1,%2,%3}, [%4];"
                 : "=r"(r[0]), "=r"(r[1]), "=r"(r[2]), "=r"(r[3]) : "r"(addr));
}
// f16 MMA (GEMM2)
__device__ __forceinline__ void mma16816(float* d, const uint32_t* a, const uint32_t* b) {
    asm volatile("mma.sync.aligned.m16n8k16.row.col.f32.f16.f16.f32 "
                 "{%0,%1,%2,%3}, {%4,%5,%6,%7}, {%8,%9}, {%0,%1,%2,%3};"
                 : "+f"(d[0]), "+f"(d[1]), "+f"(d[2]), "+f"(d[3])
                 : "r"(a[0]), "r"(a[1]), "r"(a[2]), "r"(a[3]), "r"(b[0]), "r"(b[1]));
}
// s8 k32 MMA, s32 accumulate (GEMM1)
__device__ __forceinline__ void mma16832s8(int32_t* d, const uint32_t* a, const uint32_t* b) {
    asm volatile("mma.sync.aligned.m16n8k32.row.col.s32.s8.s8.s32 "
                 "{%0,%1,%2,%3}, {%4,%5,%6,%7}, {%8,%9}, {%0,%1,%2,%3};"
                 : "+r"(d[0]), "+r"(d[1]), "+r"(d[2]), "+r"(d[3])
                 : "r"(a[0]), "r"(a[1]), "r"(a[2]), "r"(a[3]), "r"(b[0]), "r"(b[1]));
}

// ---------------- small kernels ---------------------------------------------
__global__ void wsq_kernel(const float* __restrict__ W, float* __restrict__ wsq) {
    const int n = blockIdx.x, tid = threadIdx.x;
    const float4 v = *reinterpret_cast<const float4*>(W + (size_t)n * DIM + tid * 4);
    float s = v.x * v.x + v.y * v.y + v.z * v.z + v.w * v.w;
    __shared__ float red[256];
    red[tid] = s;
    __syncthreads();
    #pragma unroll
    for (int st = 128; st > 0; st >>= 1) {
        if (tid < st) red[tid] += red[tid + st];
        __syncthreads();
    }
    if (tid == 0) wsq[n] = red[0];
}

// 2-limb int8 quantization: q0 = rn(v*s0) clamped, q1 = rn((v - q0/s0)*s1) clamped.
__device__ __forceinline__ int q8(float v) {
    return max(-127, min(127, __float2int_rn(v)));
}
__global__ void quant_kernel(const float* __restrict__ src,
                             int* __restrict__ a0, int* __restrict__ a1,
                             int n4, float s0, float inv_s0, float s1) {
    int i = blockIdx.x * blockDim.x + threadIdx.x;
    if (i >= n4) return;
    float4 v = reinterpret_cast<const float4*>(src)[i];
    int q0x = q8(v.x * s0), q0y = q8(v.y * s0), q0z = q8(v.z * s0), q0w = q8(v.w * s0);
    int q1x = q8((v.x - q0x * inv_s0) * s1);
    int q1y = q8((v.y - q0y * inv_s0) * s1);
    int q1z = q8((v.z - q0z * inv_s0) * s1);
    int q1w = q8((v.w - q0w * inv_s0) * s1);
    a0[i] = (q0x & 0xff) | ((q0y & 0xff) << 8) | ((q0z & 0xff) << 16) | ((q0w & 0xff) << 24);
    a1[i] = (q1x & 0xff) | ((q1y & 0xff) << 8) | ((q1z & 0xff) << 16) | ((q1w & 0xff) << 24);
}

// W[n][d] -> WT[d][n], fp16. block (32,32), grid (32,32).
__global__ void wt_split_kernel(const float* __restrict__ W,
                                __half* __restrict__ WThi) {
    __shared__ float tile[32][33];
    const int tx = threadIdx.x, ty = threadIdx.y;
    const int bd = blockIdx.x, bn = blockIdx.y;
    tile[ty][tx] = W[(size_t)(bn * 32 + ty) * DIM + bd * 32 + tx];
    __syncthreads();
    WThi[(size_t)(bd * 32 + ty) * NCODE + bn * 32 + tx] = __float2half_rn(tile[tx][ty]);
}

// per-row double softmax + product + normalize; emits fp16 P.
__global__ void combine_kernel(const float* __restrict__ L,
                               __half* __restrict__ Phi) {
    const int b = blockIdx.x, tid = threadIdx.x;
    const int lane = tid & 31, wp = tid >> 5;
    const float* row = L + (size_t)b * 1024;

    __shared__ float sh_e[1024 + 32];  // stride-33 padded
    __shared__ float wred[8];
    __shared__ float RS[32], CS[32];
    __shared__ float sh_bcast[2];

    const int n0 = tid * 4;
    float4 v = *reinterpret_cast<const float4*>(row + n0);

    float m = fmaxf(fmaxf(v.x, v.y), fmaxf(v.z, v.w));
    #pragma unroll
    for (int s = 16; s > 0; s >>= 1)
        m = fmaxf(m, __shfl_xor_sync(0xffffffffu, m, s));
    if (lane == 0) wred[wp] = m;
    __syncthreads();
    if (tid == 0) {
        float mm = wred[0];
        #pragma unroll
        for (int i = 1; i < 8; i++) mm = fmaxf(mm, wred[i]);
        sh_bcast[0] = mm;
    }
    __syncthreads();
    const float M = sh_bcast[0];

    const float e0 = expf(v.x - M), e1 = expf(v.y - M);
    const float e2 = expf(v.z - M), e3 = expf(v.w - M);
    sh_e[(n0 + 0) + ((n0 + 0) >> 5)] = e0;
    sh_e[(n0 + 1) + ((n0 + 1) >> 5)] = e1;
    sh_e[(n0 + 2) + ((n0 + 2) >> 5)] = e2;
    sh_e[(n0 + 3) + ((n0 + 3) >> 5)] = e3;
    __syncthreads();

    if (tid < 32) {
        float s = 0.f;
        #pragma unroll
        for (int j = 0; j < 32; j++) s += sh_e[tid * 33 + j];
        RS[tid] = s;
    } else if (tid < 64) {
        const int g2 = tid - 32;
        float s = 0.f;
        #pragma unroll
        for (int j = 0; j < 32; j++) s += sh_e[j * 33 + g2];
        CS[g2] = s;
    }
    __syncthreads();

    const int g1 = n0 >> 5, g2 = n0 & 31;
    const float rs = RS[g1];
    const float c0 = e0 * e0 / (rs * CS[g2 + 0]);
    const float c1 = e1 * e1 / (rs * CS[g2 + 1]);
    const float c2 = e2 * e2 / (rs * CS[g2 + 2]);
    const float c3 = e3 * e3 / (rs * CS[g2 + 3]);

    float s = c0 + c1 + c2 + c3;
    #pragma unroll
    for (int st = 16; st > 0; st >>= 1)
        s += __shfl_xor_sync(0xffffffffu, s, st);
    if (lane == 0) wred[wp] = s;
    __syncthreads();
    if (tid == 0) {
        float ss = 0.f;
        #pragma unroll
        for (int i = 0; i < 8; i++) ss += wred[i];
        sh_bcast[1] = 1.0f / (ss + 1e-8f);
    }
    __syncthreads();
    const float inv = sh_bcast[1];

    __half h0 = __float2half_rn(c0 * inv), h1 = __float2half_rn(c1 * inv);
    __half h2 = __float2half_rn(c2 * inv), h3 = __float2half_rn(c3 * inv);
    __half2* ph = reinterpret_cast<__half2*>(Phi + (size_t)b * 1024 + n0);
    ph[0] = __halves2half2(h0, h1); ph[1] = __halves2half2(h2, h3);
}

// ---------------- GEMM1: int8 4-term, exact s32 ------------------------------
// CTA 128x128, 256 threads = 8 warps (2m x 4n), warp tile 64x32.
// K-stage 128 int8 (128B SW128 rows), 3-stage cp.async pipeline, 8 stages.
// logits = 2^-11*acc1 + 2^-19*acc2 + 2^-27*acc3 - wsq
#define TILE8    16384                 // 128 rows x 128B (one int8 limb tile)
#define TSTAGES8 8                     // 1024 / 128

__global__ __launch_bounds__(256, 1)
void mma_gemm_s8(const int8_t* __restrict__ A0, const int8_t* __restrict__ A1,
                 const int8_t* __restrict__ B0, const int8_t* __restrict__ B1,
                 float* __restrict__ C, const float* __restrict__ wsq)
{
    constexpr uint32_t OFF_A1 = TILE8;
    constexpr uint32_t OFF_B0 = 2 * TILE8;
    constexpr uint32_t OFF_B1 = 3 * TILE8;
    constexpr uint32_t STAGE_B = 4 * TILE8;

    extern __shared__ char dyn[];
    const uint32_t sbase = (s2u(dyn) + 1023u) & ~1023u;

    const int tid  = threadIdx.x;
    const int w    = tid >> 5, lane = tid & 31;
    const int nT   = blockIdx.x, mT = blockIdx.y;
    const int wm   = (w >> 2) * 64;    // 2 warps along m
    const int wn   = (w & 3) * 32;     // 4 warps along n

    // ---- gmem loader: thread covers row tid>>1, 64B half-row, 4x16B --------
    const int lr = tid >> 1;
    const uint32_t lc = (tid & 1) * 64;
    uint32_t lso[4];
    #pragma unroll
    for (int i = 0; i < 4; i++) lso[i] = swz128((uint32_t)lr * 128u + lc + i * 16);

    const char* gA0 = (const char*)A0 + (size_t)(mT * 128 + lr) * 1024 + lc;
    const char* gA1 = (const char*)A1 + (size_t)(mT * 128 + lr) * 1024 + lc;
    const char* gB0 = (const char*)B0 + (size_t)(nT * 128 + lr) * 1024 + lc;
    const char* gB1 = (const char*)B1 + (size_t)(nT * 128 + lr) * 1024 + lc;

    auto load_stage = [&](int t, int slot) {
        const uint32_t sb = sbase + (uint32_t)slot * STAGE_B;
        const size_t tb = (size_t)t * 128;   // 128 int8 = 128B along K
        #pragma unroll
        for (int i = 0; i < 4; i++) {
            const size_t go = tb + i * 16;
            cpa16(sb + lso[i], gA0 + go);
            cpa16(sb + OFF_A1 + lso[i], gA1 + go);
            cpa16(sb + OFF_B0 + lso[i], gB0 + go);
            cpa16(sb + OFF_B1 + lso[i], gB1 + go);
        }
        CP_COMMIT();
    };

    // ---- ldmatrix bases (identical byte layout to the f16 k16 case) --------
    uint32_t a0[4];
    {
        const int rsel = (lane >> 4) * 16;
        #pragma unroll
        for (int mi = 0; mi < 4; mi++) {
            const int row = wm + mi * 16 + (lane & 15);
            a0[mi] = (uint32_t)row * 128u + (uint32_t)(rsel ^ ((row & 7) << 4));
        }
    }
    uint32_t b0[2];
    {
        const int selb = ((lane >> 3) & 1) * 16;
        #pragma unroll
        for (int p = 0; p < 2; p++) {
            const int row = wn + p * 16 + ((lane >> 4) << 3) + (lane & 7);
            b0[p] = (uint32_t)row * 128u + (uint32_t)(selb ^ ((row & 7) << 4));
        }
    }

    int32_t d1[4][4][4], d2[4][4][4], d3[4][4][4];
    #pragma unroll
    for (int i = 0; i < 4; i++)
        #pragma unroll
        for (int j = 0; j < 4; j++)
            #pragma unroll
            for (int k = 0; k < 4; k++) { d1[i][j][k] = 0; d2[i][j][k] = 0; d3[i][j][k] = 0; }

    load_stage(0, 0);
    load_stage(1, 1);

    for (int t = 0; t < TSTAGES8; t++) {
        if (t + 2 < TSTAGES8) {
            load_stage(t + 2, (t + 2) % 3);
            CP_WAIT(2);
        } else if (t + 1 < TSTAGES8) {
            CP_WAIT(1);
        } else {
            CP_WAIT(0);
        }
        __syncthreads();

        const uint32_t sb = sbase + (uint32_t)(t % 3) * STAGE_B;
        #pragma unroll
        for (int ks = 0; ks < 4; ks++) {           // 4 k32 steps per 128B row
            const uint32_t kb = (uint32_t)ks * 32;
            uint32_t bf0[8], bf1[8];
            #pragma unroll
            for (int p = 0; p < 2; p++) ldsm_x4(&bf0[p * 4], sb + OFF_B0 + (b0[p] ^ kb));
            #pragma unroll
            for (int p = 0; p < 2; p++) ldsm_x4(&bf1[p * 4], sb + OFF_B1 + (b0[p] ^ kb));
            {
                uint32_t af[16];
                #pragma unroll
                for (int mi = 0; mi < 4; mi++) ldsm_x4(&af[mi * 4], sb + (a0[mi] ^ kb));
                #pragma unroll
                for (int mi = 0; mi < 4; mi++)
                    #pragma unroll
                    for (int nj = 0; nj < 4; nj++)
                        mma16832s8(d1[mi][nj], &af[mi * 4], &bf0[(nj >> 1) * 4 + (nj & 1) * 2]);
                #pragma unroll
                for (int mi = 0; mi < 4; mi++)
                    #pragma unroll
                    for (int nj = 0; nj < 4; nj++)
                        mma16832s8(d2[mi][nj], &af[mi * 4], &bf1[(nj >> 1) * 4 + (nj & 1) * 2]);
            }
            {
                uint32_t af[16];
                #pragma unroll
                for (int mi = 0; mi < 4; mi++) ldsm_x4(&af[mi * 4], sb + OFF_A1 + (a0[mi] ^ kb));
                #pragma unroll
                for (int mi = 0; mi < 4; mi++)
                    #pragma unroll
                    for (int nj = 0; nj < 4; nj++)
                        mma16832s8(d2[mi][nj], &af[mi * 4], &bf0[(nj >> 1) * 4 + (nj & 1) * 2]);
                #pragma unroll
                for (int mi = 0; mi < 4; mi++)
                    #pragma unroll
                    for (int nj = 0; nj < 4; nj++)
                        mma16832s8(d3[mi][nj], &af[mi * 4], &bf1[(nj >> 1) * 4 + (nj & 1) * 2]);
            }
        }
        __syncthreads();
    }

    // ---- epilogue: logits = 2^-11*d1 + 2^-19*d2 + 2^-27*d3 - wsq -----------
    #pragma unroll
    for (int mi = 0; mi < 4; mi++) {
        const int row0 = mT * 128 + wm + mi * 16 + (lane >> 2);
        #pragma unroll
        for (int nj = 0; nj < 4; nj++) {
            const int col = nT * 128 + wn + nj * 8 + (lane & 3) * 2;
            const float w0 = __ldg(&wsq[col]);
            const float w1 = __ldg(&wsq[col + 1]);
            float2 o0, o1;
            o0.x = __int2float_rn(d1[mi][nj][0]) * 0x1p-11f
                 + __int2float_rn(d2[mi][nj][0]) * 0x1p-19f
                 + __int2float_rn(d3[mi][nj][0]) * 0x1p-27f - w0;
            o0.y = __int2float_rn(d1[mi][nj][1]) * 0x1p-11f
                 + __int2float_rn(d2[mi][nj][1]) * 0x1p-19f
                 + __int2float_rn(d3[mi][nj][1]) * 0x1p-27f - w1;
            o1.x = __int2float_rn(d1[mi][nj][2]) * 0x1p-11f
                 + __int2float_rn(d2[mi][nj][2]) * 0x1p-19f
                 + __int2float_rn(d3[mi][nj][2]) * 0x1p-27f - w0;
            o1.y = __int2float_rn(d1[mi][nj][3]) * 0x1p-11f
                 + __int2float_rn(d2[mi][nj][3]) * 0x1p-19f
                 + __int2float_rn(d3[mi][nj][3]) * 0x1p-27f - w1;
            *reinterpret_cast<float2*>(C + (size_t)row0 * 1024 + col) = o0;
            *reinterpret_cast<float2*>(C + (size_t)(row0 + 8) * 1024 + col) = o1;
        }
    }
}

// ---------------- GEMM2: fp16 1-term -----------------------------------------
// CTA 128x128, 256 threads = 8 warps (2m x 4n), warp tile 64x32.
// K-stage 64 f16 (128B SW128 rows), 3-stage pipeline, 16 stages.
#define TILE16   16384
#define TSTAGES  16

__global__ __launch_bounds__(256, 1)
void mma_gemm_f16(const __half* __restrict__ A, const __half* __restrict__ B,
                  float* __restrict__ C)
{
    constexpr uint32_t OFF_B = TILE16;
    constexpr uint32_t STAGE_B = 2 * TILE16;

    extern __shared__ char dyn[];
    const uint32_t sbase = (s2u(dyn) + 1023u) & ~1023u;

    const int tid  = threadIdx.x;
    const int w    = tid >> 5, lane = tid & 31;
    const int nT   = blockIdx.x, mT = blockIdx.y;
    const int wm   = (w >> 2) * 64;
    const int wn   = (w & 3) * 32;

    const int lr = tid >> 1;
    const uint32_t lc = (tid & 1) * 64;
    uint32_t lso[4];
    #pragma unroll
    for (int i = 0; i < 4; i++) lso[i] = swz128((uint32_t)lr * 128u + lc + i * 16);

    const char* gA = (const char*)A + (size_t)(mT * 128 + lr) * 2048 + lc;
    const char* gB = (const char*)B + (size_t)(nT * 128 + lr) * 2048 + lc;

    auto load_stage = [&](int t, int slot) {
        const uint32_t sb = sbase + (uint32_t)slot * STAGE_B;
        const size_t tb = (size_t)t * 128;
        #pragma unroll
        for (int i = 0; i < 4; i++) {
            const size_t go = tb + i * 16;
            cpa16(sb + lso[i], gA + go);
            cpa16(sb + OFF_B + lso[i], gB + go);
        }
        CP_COMMIT();
    };

    uint32_t a0[4];
    {
        const int rsel = (lane >> 4) * 16;
        #pragma unroll
        for (int mi = 0; mi < 4; mi++) {
            const int row = wm + mi * 16 + (lane & 15);
            a0[mi] = (uint32_t)row * 128u + (uint32_t)(rsel ^ ((row & 7) << 4));
        }
    }
    uint32_t b0[2];
    {
        const int selb = ((lane >> 3) & 1) * 16;
        #pragma unroll
        for (int p = 0; p < 2; p++) {
            const int row = wn + p * 16 + ((lane >> 4) << 3) + (lane & 7);
            b0[p] = (uint32_t)row * 128u + (uint32_t)(selb ^ ((row & 7) << 4));
        }
    }

    float d[4][4][4];
    #pragma unroll
    for (int i = 0; i < 4; i++)
        #pragma unroll
        for (int j = 0; j < 4; j++)
            #pragma unroll
            for (int k = 0; k < 4; k++) d[i][j][k] = 0.f;

    load_stage(0, 0);
    load_stage(1, 1);

    for (int t = 0; t < TSTAGES; t++) {
        if (t + 2 < TSTAGES) {
            load_stage(t + 2, (t + 2) % 3);
            CP_WAIT(2);
        } else if (t + 1 < TSTAGES) {
            CP_WAIT(1);
        } else {
            CP_WAIT(0);
        }
        __syncthreads();

        const uint32_t sb = sbase + (uint32_t)(t % 3) * STAGE_B;
        #pragma unroll
        for (int k16 = 0; k16 < 4; k16++) {
            const uint32_t kb = (uint32_t)k16 * 32;
            uint32_t ah[16], bh[8];
            #pragma unroll
            for (int mi = 0; mi < 4; mi++) ldsm_x4(&ah[mi * 4], sb + (a0[mi] ^ kb));
            #pragma unroll
            for (int p = 0; p < 2; p++) ldsm_x4(&bh[p * 4], sb + OFF_B + (b0[p] ^ kb));
            #pragma unroll
            for (int mi = 0; mi < 4; mi++)
                #pragma unroll
                for (int nj = 0; nj < 4; nj++)
                    mma16816(d[mi][nj], &ah[mi * 4], &bh[(nj >> 1) * 4 + (nj & 1) * 2]);
        }
        __syncthreads();
    }

    #pragma unroll
    for (int mi = 0; mi < 4; mi++) {
        const int row0 = mT * 128 + wm + mi * 16 + (lane >> 2);
        #pragma unroll
        for (int nj = 0; nj < 4; nj++) {
            const int col = nT * 128 + wn + nj * 8 + (lane & 3) * 2;
            float2 o0, o1;
            o0.x = d[mi][nj][0]; o0.y = d[mi][nj][1];
            o1.x = d[mi][nj][2]; o1.y = d[mi][nj][3];
            *reinterpret_cast<float2*>(C + (size_t)row0 * 1024 + col) = o0;
            *reinterpret_cast<float2*>(C + (size_t)(row0 + 8) * 1024 + col) = o1;
        }
    }
}

// ---------------------------------------------------------------------------
extern "C" void kernel_launch(void* const* d_in, const int* in_sizes, int n_in,
                              void* d_out, int out_size) {
    const float* x = (const float*)d_in[0];   // [16384, 1024]
    const float* w = (const float*)d_in[1];   // [32, 32, 1024] = [1024, 1024]
    float* out = (float*)d_out;               // [16384, 1024]

    float *logits, *wsq;
    int8_t *xa0, *xa1, *wb0, *wb1;
    __half *wthi, *phi;
    cudaGetSymbolAddress((void**)&logits, g_logits);
    cudaGetSymbolAddress((void**)&wsq,    g_wsq);
    cudaGetSymbolAddress((void**)&xa0,    g_xa0);
    cudaGetSymbolAddress((void**)&xa1,    g_xa1);
    cudaGetSymbolAddress((void**)&wb0,    g_wb0);
    cudaGetSymbolAddress((void**)&wb1,    g_wb1);
    cudaGetSymbolAddress((void**)&wthi,   g_wthi);
    cudaGetSymbolAddress((void**)&phi,    g_phi);

    const int SMEM1 = 3 * 4 * TILE8 + 1024;    // 197632 B
    const int SMEM2 = 3 * 2 * TILE16 + 1024;   //  99328 B
    cudaFuncSetAttribute(mma_gemm_s8,  cudaFuncAttributeMaxDynamicSharedMemorySize, SMEM1);
    cudaFuncSetAttribute(mma_gemm_f16, cudaFuncAttributeMaxDynamicSharedMemorySize, SMEM2);

    // prologue
    wsq_kernel<<<NCODE, 256>>>(w, wsq);
    const int xn4 = BROWS * DIM / 4;
    quant_kernel<<<(xn4 + 255) / 256, 256>>>(x, (int*)xa0, (int*)xa1, xn4,
                                             16.f, 0x1p-4f, 4096.f);
    const int wn4 = NCODE * DIM / 4;
    quant_kernel<<<(wn4 + 255) / 256, 256>>>(w, (int*)wb0, (int*)wb1, wn4,
                                             256.f, 0x1p-8f, 65536.f);
    wt_split_kernel<<<dim3(32, 32), dim3(32, 32)>>>(w, wthi);

    // GEMM1 (int8 exact): logits = 2*x@W^T - wsq
    mma_gemm_s8<<<dim3(NCODE / 128, BROWS / 128), 256, SMEM1>>>(
        xa0, xa1, wb0, wb1, logits, wsq);

    // combine: double softmax + product + normalize -> P (fp16)
    combine_kernel<<<BROWS, 256>>>(logits, phi);

    // GEMM2: out = Phi @ fp16(W)
    mma_gemm_f16<<<dim3(DIM / 128, BROWS / 128), 256, SMEM2>>>(phi, wthi, out);
}

// round 10
// speedup vs baseline: 2.2388x; 2.2388x over previous
#include <cuda_runtime.h>
#include <cuda_fp16.h>
#include <math.h>
#include <stdint.h>

// Problem shape (fixed): B=16384 rows, D=1024, grid 32x32 -> N=1024 codes
#define BROWS 16384
#define DIM   1024
#define NCODE 1024

// ---------------- scratch (__device__ globals; allocation-free rule) -------
__device__ float g_logits[(size_t)BROWS * NCODE];    // 64MB
__device__ float g_wsq[NCODE];
__device__ __half g_xhi[(size_t)BROWS * DIM];
__device__ __half g_xlo[(size_t)BROWS * DIM];
__device__ __half g_whi[(size_t)NCODE * DIM];
__device__ __half g_wlo[(size_t)NCODE * DIM];
__device__ __half g_wthi[(size_t)DIM * NCODE];
__device__ __half g_phi[(size_t)BROWS * NCODE];

// ---------------- PTX helpers ----------------------------------------------
__device__ __forceinline__ uint32_t s2u(const void* p) {
    uint32_t a;
    asm("{ .reg .u64 t; cvta.to.shared.u64 t, %1; cvt.u32.u64 %0, t; }" : "=r"(a) : "l"(p));
    return a;
}
__device__ __forceinline__ uint32_t swz128(uint32_t o) { return o ^ ((o >> 3) & 0x70); }

__device__ __forceinline__ void cpa16(uint32_t dst, const void* src) {
    asm volatile("cp.async.cg.shared.global [%0], [%1], 16;" :: "r"(dst), "l"(src));
}
#define CP_COMMIT() asm volatile("cp.async.commit_group;")
#define CP_WAIT(n)  asm volatile("cp.async.wait_group %0;" :: "n"(n))

__device__ __forceinline__ void ldsm_x4(uint32_t* r, uint32_t addr) {
    asm volatile("ldmatrix.sync.aligned.m8n8.x4.shared.b16 {%0,%1,%2,%3}, [%4];"
                 : "=r"(r[0]), "=r"(r[1]), "=r"(r[2]), "=r"(r[3]) : "r"(addr));
}
__device__ __forceinline__ void mma16816(float* d, const uint32_t* a, const uint32_t* b) {
    asm volatile("mma.sync.aligned.m16n8k16.row.col.f32.f16.f16.f32 "
                 "{%0,%1,%2,%3}, {%4,%5,%6,%7}, {%8,%9}, {%0,%1,%2,%3};"
                 : "+f"(d[0]), "+f"(d[1]), "+f"(d[2]), "+f"(d[3])
                 : "r"(a[0]), "r"(a[1]), "r"(a[2]), "r"(a[3]), "r"(b[0]), "r"(b[1]));
}
// f16-accumulator HMMA (for small correction terms)
__device__ __forceinline__ void mma16816h(uint32_t* d, const uint32_t* a, const uint32_t* b) {
    asm volatile("mma.sync.aligned.m16n8k16.row.col.f16.f16.f16.f16 "
                 "{%0,%1}, {%2,%3,%4,%5}, {%6,%7}, {%0,%1};"
                 : "+r"(d[0]), "+r"(d[1])
                 : "r"(a[0]), "r"(a[1]), "r"(a[2]), "r"(a[3]), "r"(b[0]), "r"(b[1]));
}

// ---------------- small kernels ---------------------------------------------
__global__ void wsq_kernel(const float* __restrict__ W, float* __restrict__ wsq) {
    const int n = blockIdx.x, tid = threadIdx.x;
    const float4 v = *reinterpret_cast<const float4*>(W + (size_t)n * DIM + tid * 4);
    float s = v.x * v.x + v.y * v.y + v.z * v.z + v.w * v.w;
    __shared__ float red[256];
    red[tid] = s;
    __syncthreads();
    #pragma unroll
    for (int st = 128; st > 0; st >>= 1) {
        if (tid < st) red[tid] += red[tid + st];
        __syncthreads();
    }
    if (tid == 0) wsq[n] = red[0];
}

// hi = f16(v), lo = f16(v - hi). 4 elems/thread.
__global__ void split_kernel(const float* __restrict__ src,
                             __half* __restrict__ hi, __half* __restrict__ lo, int n4) {
    int i = blockIdx.x * blockDim.x + threadIdx.x;
    if (i >= n4) return;
    float4 v = reinterpret_cast<const float4*>(src)[i];
    __half h0 = __float2half_rn(v.x), h1 = __float2half_rn(v.y);
    __half h2 = __float2half_rn(v.z), h3 = __float2half_rn(v.w);
    __half l0 = __float2half_rn(v.x - __half2float(h0));
    __half l1 = __float2half_rn(v.y - __half2float(h1));
    __half l2 = __float2half_rn(v.z - __half2float(h2));
    __half l3 = __float2half_rn(v.w - __half2float(h3));
    __half2* ph = reinterpret_cast<__half2*>(hi) + 2 * i;
    __half2* pl = reinterpret_cast<__half2*>(lo) + 2 * i;
    ph[0] = __halves2half2(h0, h1); ph[1] = __halves2half2(h2, h3);
    pl[0] = __halves2half2(l0, l1); pl[1] = __halves2half2(l2, l3);
}

// W[n][d] -> WT[d][n], fp16 (hi only). block (32,32), grid (32,32).
__global__ void wt_split_kernel(const float* __restrict__ W,
                                __half* __restrict__ WThi) {
    __shared__ float tile[32][33];
    const int tx = threadIdx.x, ty = threadIdx.y;
    const int bd = blockIdx.x, bn = blockIdx.y;
    tile[ty][tx] = W[(size_t)(bn * 32 + ty) * DIM + bd * 32 + tx];
    __syncthreads();
    WThi[(size_t)(bd * 32 + ty) * NCODE + bn * 32 + tx] = __float2half_rn(tile[tx][ty]);
}

// per-row double softmax + product + normalize; emits fp16 P.
// fast-math: __expf + reciprocal-multiply (no per-element divides).
__global__ void combine_kernel(const float* __restrict__ L,
                               __half* __restrict__ Phi) {
    const int b = blockIdx.x, tid = threadIdx.x;
    const int lane = tid & 31, wp = tid >> 5;
    const float* row = L + (size_t)b * 1024;

    __shared__ float sh_e[1024 + 32];  // stride-33 padded
    __shared__ float wred[8];
    __shared__ float iRS[32], iCS[32]; // reciprocals of row/col sums
    __shared__ float sh_bcast[2];

    const int n0 = tid * 4;
    float4 v = *reinterpret_cast<const float4*>(row + n0);

    // global max: warp shuffle then 8->1
    float m = fmaxf(fmaxf(v.x, v.y), fmaxf(v.z, v.w));
    #pragma unroll
    for (int s = 16; s > 0; s >>= 1)
        m = fmaxf(m, __shfl_xor_sync(0xffffffffu, m, s));
    if (lane == 0) wred[wp] = m;
    __syncthreads();
    if (tid == 0) {
        float mm = wred[0];
        #pragma unroll
        for (int i = 1; i < 8; i++) mm = fmaxf(mm, wred[i]);
        sh_bcast[0] = mm;
    }
    __syncthreads();
    const float M = sh_bcast[0];

    const float e0 = __expf(v.x - M), e1 = __expf(v.y - M);
    const float e2 = __expf(v.z - M), e3 = __expf(v.w - M);
    sh_e[(n0 + 0) + ((n0 + 0) >> 5)] = e0;
    sh_e[(n0 + 1) + ((n0 + 1) >> 5)] = e1;
    sh_e[(n0 + 2) + ((n0 + 2) >> 5)] = e2;
    sh_e[(n0 + 3) + ((n0 + 3) >> 5)] = e3;
    __syncthreads();

    if (tid < 32) {
        float s = 0.f;
        #pragma unroll
        for (int j = 0; j < 32; j++) s += sh_e[tid * 33 + j];
        iRS[tid] = __fdividef(1.f, s);
    } else if (tid < 64) {
        const int g2 = tid - 32;
        float s = 0.f;
        #pragma unroll
        for (int j = 0; j < 32; j++) s += sh_e[j * 33 + g2];
        iCS[g2] = __fdividef(1.f, s);
    }
    __syncthreads();

    const int g1 = n0 >> 5, g2 = n0 & 31;
    const float irs = iRS[g1];
    const float c0 = e0 * e0 * irs * iCS[g2 + 0];
    const float c1 = e1 * e1 * irs * iCS[g2 + 1];
    const float c2 = e2 * e2 * irs * iCS[g2 + 2];
    const float c3 = e3 * e3 * irs * iCS[g2 + 3];

    float s = c0 + c1 + c2 + c3;
    #pragma unroll
    for (int st = 16; st > 0; st >>= 1)
        s += __shfl_xor_sync(0xffffffffu, s, st);
    if (lane == 0) wred[wp] = s;
    __syncthreads();
    if (tid == 0) {
        float ss = 0.f;
        #pragma unroll
        for (int i = 0; i < 8; i++) ss += wred[i];
        sh_bcast[1] = __fdividef(1.0f, ss + 1e-8f);
    }
    __syncthreads();
    const float inv = sh_bcast[1];

    __half h0 = __float2half_rn(c0 * inv), h1 = __float2half_rn(c1 * inv);
    __half h2 = __float2half_rn(c2 * inv), h3 = __float2half_rn(c3 * inv);
    __half2* ph = reinterpret_cast<__half2*>(Phi + (size_t)b * 1024 + n0);
    ph[0] = __halves2half2(h0, h1); ph[1] = __halves2half2(h2, h3);
}

// ---------------- mma.sync split-fp16 GEMM -----------------------------------
// CTA 128x128, 256 threads = 8 warps (2m x 4n), warp tile 64x32.
// K-stage 64 (128B SW128 rows), 3-stage cp.async pipeline.
// TERMS==3: Ahi*Bhi (f32 acc) + [Alo*Bhi + Ahi*Blo] (shared f16 acc).
// TERMS==1: Ahi*Bhi (f32 acc).
// EPI==1:   C = 2*acc - wsq[col].
#define TILE16   16384                 // one 128x64 f16 tile (128 rows x 128B)
#define TSTAGES  16                    // 1024 / 64

template<int EPI, int TERMS>
__global__ __launch_bounds__(256, 1)
void mma_gemm(const __half* __restrict__ Ahi, const __half* __restrict__ Alo,
              const __half* __restrict__ Bhi, const __half* __restrict__ Blo,
              float* __restrict__ C, const float* __restrict__ wsq)
{
    constexpr bool HAS_CORR = (TERMS == 3);
    constexpr uint32_t NTILES  = HAS_CORR ? 4 : 2;
    constexpr uint32_t STAGE_B = NTILES * TILE16;
    constexpr uint32_t OFF_ALO = TILE16;
    constexpr uint32_t OFF_BHI = (HAS_CORR ? 2 : 1) * TILE16;
    constexpr uint32_t OFF_BLO = 3 * TILE16;

    extern __shared__ char dyn[];
    const uint32_t sbase = (s2u(dyn) + 1023u) & ~1023u;

    const int tid  = threadIdx.x;
    const int w    = tid >> 5, lane = tid & 31;
    const int nT   = blockIdx.x, mT = blockIdx.y;
    const int wm   = (w >> 2) * 64;    // 2 warps along m
    const int wn   = (w & 3) * 32;     // 4 warps along n

    // ---- gmem loader geometry: thread covers row tid>>1, 64B half-row ------
    const int lr = tid >> 1;
    const uint32_t lc = (tid & 1) * 64;
    uint32_t lso[4];
    #pragma unroll
    for (int i = 0; i < 4; i++) lso[i] = swz128((uint32_t)lr * 128u + lc + i * 16);

    const char* gAhi = (const char*)Ahi + (size_t)(mT * 128 + lr) * 2048 + lc;
    const char* gAlo = HAS_CORR ? (const char*)Alo + (size_t)(mT * 128 + lr) * 2048 + lc : nullptr;
    const char* gBhi = (const char*)Bhi + (size_t)(nT * 128 + lr) * 2048 + lc;
    const char* gBlo = HAS_CORR ? (const char*)Blo + (size_t)(nT * 128 + lr) * 2048 + lc : nullptr;

    auto load_stage = [&](int t, int slot) {
        const uint32_t sb = sbase + (uint32_t)slot * STAGE_B;
        const size_t tb = (size_t)t * 128;   // 64 f16 = 128B along K
        #pragma unroll
        for (int i = 0; i < 4; i++) {
            const size_t go = tb + i * 16;
            cpa16(sb + lso[i], gAhi + go);
            if (HAS_CORR) cpa16(sb + OFF_ALO + lso[i], gAlo + go);
            cpa16(sb + OFF_BHI + lso[i], gBhi + go);
            if (HAS_CORR) cpa16(sb + OFF_BLO + lso[i], gBlo + go);
        }
        CP_COMMIT();
    };

    // ---- ldmatrix base addresses (swizzled; k-step folds in via XOR) -------
    uint32_t a0[4];
    {
        const int rsel = (lane >> 4) * 16;
        #pragma unroll
        for (int mi = 0; mi < 4; mi++) {
            const int row = wm + mi * 16 + (lane & 15);
            a0[mi] = (uint32_t)row * 128u + (uint32_t)(rsel ^ ((row & 7) << 4));
        }
    }
    uint32_t b0[2];
    {
        const int selb = ((lane >> 3) & 1) * 16;
        #pragma unroll
        for (int p = 0; p < 2; p++) {
            const int row = wn + p * 16 + ((lane >> 4) << 3) + (lane & 7);
            b0[p] = (uint32_t)row * 128u + (uint32_t)(selb ^ ((row & 7) << 4));
        }
    }

    float d[4][4][4];
    #pragma unroll
    for (int i = 0; i < 4; i++)
        #pragma unroll
        for (int j = 0; j < 4; j++)
            #pragma unroll
            for (int k = 0; k < 4; k++) d[i][j][k] = 0.f;

    uint32_t dc[4][4][2];   // shared f16 accumulator for both corrections
    if (HAS_CORR) {
        #pragma unroll
        for (int i = 0; i < 4; i++)
            #pragma unroll
            for (int j = 0; j < 4; j++) { dc[i][j][0] = 0u; dc[i][j][1] = 0u; }
    }

    load_stage(0, 0);
    load_stage(1, 1);

    for (int t = 0; t < TSTAGES; t++) {
        if (t + 2 < TSTAGES) {
            load_stage(t + 2, (t + 2) % 3);
            CP_WAIT(2);
        } else if (t + 1 < TSTAGES) {
            CP_WAIT(1);
        } else {
            CP_WAIT(0);
        }
        __syncthreads();

        const uint32_t sb = sbase + (uint32_t)(t % 3) * STAGE_B;
        #pragma unroll
        for (int k16 = 0; k16 < 4; k16++) {
            const uint32_t kb = (uint32_t)k16 * 32;
            uint32_t ah[16], al[16], bh[8], bl[8];
            #pragma unroll
            for (int mi = 0; mi < 4; mi++) ldsm_x4(&ah[mi * 4], sb + (a0[mi] ^ kb));
            if (HAS_CORR) {
                #pragma unroll
                for (int mi = 0; mi < 4; mi++) ldsm_x4(&al[mi * 4], sb + OFF_ALO + (a0[mi] ^ kb));
            }
            #pragma unroll
            for (int p = 0; p < 2; p++) ldsm_x4(&bh[p * 4], sb + OFF_BHI + (b0[p] ^ kb));
            if (HAS_CORR) {
                #pragma unroll
                for (int p = 0; p < 2; p++) ldsm_x4(&bl[p * 4], sb + OFF_BLO + (b0[p] ^ kb));
            }
            // main term: f32 accumulators
            #pragma unroll
            for (int mi = 0; mi < 4; mi++)
                #pragma unroll
                for (int nj = 0; nj < 4; nj++)
                    mma16816(d[mi][nj], &ah[mi * 4], &bh[(nj >> 1) * 4 + (nj & 1) * 2]);
            // corrections: f16 accumulators (shared fragment)
            if (HAS_CORR) {
                #pragma unroll
                for (int mi = 0; mi < 4; mi++)
                    #pragma unroll
                    for (int nj = 0; nj < 4; nj++)
                        mma16816h(dc[mi][nj], &al[mi * 4], &bh[(nj >> 1) * 4 + (nj & 1) * 2]);
                #pragma unroll
                for (int mi = 0; mi < 4; mi++)
                    #pragma unroll
                    for (int nj = 0; nj < 4; nj++)
                        mma16816h(dc[mi][nj], &ah[mi * 4], &bl[(nj >> 1) * 4 + (nj & 1) * 2]);
            }
        }
        __syncthreads();
    }

    // ---- epilogue -----------------------------------------------------------
    #pragma unroll
    for (int mi = 0; mi < 4; mi++) {
        const int row0 = mT * 128 + wm + mi * 16 + (lane >> 2);
        #pragma unroll
        for (int nj = 0; nj < 4; nj++) {
            const int col = nT * 128 + wn + nj * 8 + (lane & 3) * 2;
            float v0 = d[mi][nj][0], v1 = d[mi][nj][1];
            float v2 = d[mi][nj][2], v3 = d[mi][nj][3];
            if (HAS_CORR) {
                const __half2 c01 = *reinterpret_cast<const __half2*>(&dc[mi][nj][0]);
                const __half2 c23 = *reinterpret_cast<const __half2*>(&dc[mi][nj][1]);
                v0 += __half2float(c01.x); v1 += __half2float(c01.y);
                v2 += __half2float(c23.x); v3 += __half2float(c23.y);
            }
            float2 o0, o1;
            if (EPI == 1) {
                const float w0 = __ldg(&wsq[col]);
                const float w1 = __ldg(&wsq[col + 1]);
                o0.x = 2.f * v0 - w0; o0.y = 2.f * v1 - w1;
                o1.x = 2.f * v2 - w0; o1.y = 2.f * v3 - w1;
            } else {
                o0.x = v0; o0.y = v1;
                o1.x = v2; o1.y = v3;
            }
            *reinterpret_cast<float2*>(C + (size_t)row0 * 1024 + col) = o0;
            *reinterpret_cast<float2*>(C + (size_t)(row0 + 8) * 1024 + col) = o1;
        }
    }
}

// ---------------------------------------------------------------------------
extern "C" void kernel_launch(void* const* d_in, const int* in_sizes, int n_in,
                              void* d_out, int out_size) {
    const float* x = (const float*)d_in[0];   // [16384, 1024]
    const float* w = (const float*)d_in[1];   // [32, 32, 1024] = [1024, 1024]
    float* out = (float*)d_out;               // [16384, 1024]

    float *logits, *wsq;
    __half *xhi, *xlo, *whi, *wlo, *wthi, *phi;
    cudaGetSymbolAddress((void**)&logits, g_logits);
    cudaGetSymbolAddress((void**)&wsq,    g_wsq);
    cudaGetSymbolAddress((void**)&xhi,    g_xhi);
    cudaGetSymbolAddress((void**)&xlo,    g_xlo);
    cudaGetSymbolAddress((void**)&whi,    g_whi);
    cudaGetSymbolAddress((void**)&wlo,    g_wlo);
    cudaGetSymbolAddress((void**)&wthi,   g_wthi);
    cudaGetSymbolAddress((void**)&phi,    g_phi);

    const int SMEM1 = 3 * 4 * TILE16 + 1024;   // 197632 B
    const int SMEM2 = 3 * 2 * TILE16 + 1024;   //  99328 B
    cudaFuncSetAttribute(mma_gemm<1, 3>, cudaFuncAttributeMaxDynamicSharedMemorySize, SMEM1);
    cudaFuncSetAttribute(mma_gemm<0, 1>, cudaFuncAttributeMaxDynamicSharedMemorySize, SMEM2);

    // prologue conversions
    wsq_kernel<<<NCODE, 256>>>(w, wsq);
    const int xn4 = BROWS * DIM / 4;
    split_kernel<<<(xn4 + 255) / 256, 256>>>(x, xhi, xlo, xn4);
    const int wn4 = NCODE * DIM / 4;
    split_kernel<<<(wn4 + 255) / 256, 256>>>(w, whi, wlo, wn4);
    wt_split_kernel<<<dim3(32, 32), dim3(32, 32)>>>(w, wthi);

    // GEMM1: logits = 2*x@W^T - wsq   (x_sq cancels under the softmaxes)
    mma_gemm<1, 3><<<dim3(NCODE / 128, BROWS / 128), 256, SMEM1>>>(
        xhi, xlo, whi, wlo, logits, wsq);

    // combine: double softmax + product + normalize -> P (fp16)
    combine_kernel<<<BROWS, 256>>>(logits, phi);

    // GEMM2: out = Phi @ fp16(W)   (1 term; B operand = W^T, K-major)
    mma_gemm<0, 1><<<dim3(DIM / 128, BROWS / 128), 256, SMEM2>>>(
        phi, nullptr, wthi, nullptr, out, nullptr);
}

// round 11
// speedup vs baseline: 2.6823x; 1.1981x over previous
#include <cuda_runtime.h>
#include <cuda_fp16.h>
#include <math.h>
#include <stdint.h>

// Problem shape (fixed): B=16384 rows, D=1024, grid 32x32 -> N=1024 codes
#define BROWS 16384
#define DIM   1024
#define NCODE 1024

// ---------------- scratch (__device__ globals; allocation-free rule) -------
__device__ float g_logits[(size_t)BROWS * NCODE];    // 64MB
__device__ float g_wsq[NCODE];
__device__ __half g_xhi[(size_t)BROWS * DIM];
__device__ __half g_xlo[(size_t)BROWS * DIM];
__device__ __half g_whi[(size_t)NCODE * DIM];
__device__ __half g_wthi[(size_t)DIM * NCODE];
__device__ __half g_phi[(size_t)BROWS * NCODE];

// ---------------- PTX helpers ----------------------------------------------
__device__ __forceinline__ uint32_t s2u(const void* p) {
    uint32_t a;
    asm("{ .reg .u64 t; cvta.to.shared.u64 t, %1; cvt.u32.u64 %0, t; }" : "=r"(a) : "l"(p));
    return a;
}
__device__ __forceinline__ uint32_t swz128(uint32_t o) { return o ^ ((o >> 3) & 0x70); }

__device__ __forceinline__ void cpa16(uint32_t dst, const void* src) {
    asm volatile("cp.async.cg.shared.global [%0], [%1], 16;" :: "r"(dst), "l"(src));
}
#define CP_COMMIT() asm volatile("cp.async.commit_group;")
#define CP_WAIT(n)  asm volatile("cp.async.wait_group %0;" :: "n"(n))

__device__ __forceinline__ void ldsm_x4(uint32_t* r, uint32_t addr) {
    asm volatile("ldmatrix.sync.aligned.m8n8.x4.shared.b16 {%0,%1,%2,%3}, [%4];"
                 : "=r"(r[0]), "=r"(r[1]), "=r"(r[2]), "=r"(r[3]) : "r"(addr));
}
__device__ __forceinline__ void mma16816(float* d, const uint32_t* a, const uint32_t* b) {
    asm volatile("mma.sync.aligned.m16n8k16.row.col.f32.f16.f16.f32 "
                 "{%0,%1,%2,%3}, {%4,%5,%6,%7}, {%8,%9}, {%0,%1,%2,%3};"
                 : "+f"(d[0]), "+f"(d[1]), "+f"(d[2]), "+f"(d[3])
                 : "r"(a[0]), "r"(a[1]), "r"(a[2]), "r"(a[3]), "r"(b[0]), "r"(b[1]));
}
// f16-accumulator HMMA (for small correction term)
__device__ __forceinline__ void mma16816h(uint32_t* d, const uint32_t* a, const uint32_t* b) {
    asm volatile("mma.sync.aligned.m16n8k16.row.col.f16.f16.f16.f16 "
                 "{%0,%1}, {%2,%3,%4,%5}, {%6,%7}, {%0,%1};"
                 : "+r"(d[0]), "+r"(d[1])
                 : "r"(a[0]), "r"(a[1]), "r"(a[2]), "r"(a[3]), "r"(b[0]), "r"(b[1]));
}

// ---------------- small kernels ---------------------------------------------
__global__ void wsq_kernel(const float* __restrict__ W, float* __restrict__ wsq) {
    const int n = blockIdx.x, tid = threadIdx.x;
    const float4 v = *reinterpret_cast<const float4*>(W + (size_t)n * DIM + tid * 4);
    float s = v.x * v.x + v.y * v.y + v.z * v.z + v.w * v.w;
    __shared__ float red[256];
    red[tid] = s;
    __syncthreads();
    #pragma unroll
    for (int st = 128; st > 0; st >>= 1) {
        if (tid < st) red[tid] += red[tid + st];
        __syncthreads();
    }
    if (tid == 0) wsq[n] = red[0];
}

// hi = f16(v), lo = f16(v - hi). 4 elems/thread. (x only)
__global__ void split_kernel(const float* __restrict__ src,
                             __half* __restrict__ hi, __half* __restrict__ lo, int n4) {
    int i = blockIdx.x * blockDim.x + threadIdx.x;
    if (i >= n4) return;
    float4 v = reinterpret_cast<const float4*>(src)[i];
    __half h0 = __float2half_rn(v.x), h1 = __float2half_rn(v.y);
    __half h2 = __float2half_rn(v.z), h3 = __float2half_rn(v.w);
    __half l0 = __float2half_rn(v.x - __half2float(h0));
    __half l1 = __float2half_rn(v.y - __half2float(h1));
    __half l2 = __float2half_rn(v.z - __half2float(h2));
    __half l3 = __float2half_rn(v.w - __half2float(h3));
    __half2* ph = reinterpret_cast<__half2*>(hi) + 2 * i;
    __half2* pl = reinterpret_cast<__half2*>(lo) + 2 * i;
    ph[0] = __halves2half2(h0, h1); ph[1] = __halves2half2(h2, h3);
    pl[0] = __halves2half2(l0, l1); pl[1] = __halves2half2(l2, l3);
}

// W prep (fused): whi[n][d] = f16(W[n][d]); wthi[d][n] = f16(W[n][d]).
// block (32,32), grid (32,32).
__global__ void wprep_kernel(const float* __restrict__ W,
                             __half* __restrict__ Whi,
                             __half* __restrict__ WThi) {
    __shared__ float tile[32][33];
    const int tx = threadIdx.x, ty = threadIdx.y;
    const int bd = blockIdx.x, bn = blockIdx.y;
    const float v = W[(size_t)(bn * 32 + ty) * DIM + bd * 32 + tx];
    tile[ty][tx] = v;
    Whi[(size_t)(bn * 32 + ty) * DIM + bd * 32 + tx] = __float2half_rn(v);
    __syncthreads();
    WThi[(size_t)(bd * 32 + ty) * NCODE + bn * 32 + tx] = __float2half_rn(tile[tx][ty]);
}

// per-row double softmax + product + normalize; emits fp16 P.
__global__ void combine_kernel(const float* __restrict__ L,
                               __half* __restrict__ Phi) {
    const int b = blockIdx.x, tid = threadIdx.x;
    const int lane = tid & 31, wp = tid >> 5;
    const float* row = L + (size_t)b * 1024;

    __shared__ float sh_e[1024 + 32];  // stride-33 padded
    __shared__ float wred[8];
    __shared__ float iRS[32], iCS[32];
    __shared__ float sh_bcast[2];

    const int n0 = tid * 4;
    float4 v = *reinterpret_cast<const float4*>(row + n0);

    float m = fmaxf(fmaxf(v.x, v.y), fmaxf(v.z, v.w));
    #pragma unroll
    for (int s = 16; s > 0; s >>= 1)
        m = fmaxf(m, __shfl_xor_sync(0xffffffffu, m, s));
    if (lane == 0) wred[wp] = m;
    __syncthreads();
    if (tid == 0) {
        float mm = wred[0];
        #pragma unroll
        for (int i = 1; i < 8; i++) mm = fmaxf(mm, wred[i]);
        sh_bcast[0] = mm;
    }
    __syncthreads();
    const float M = sh_bcast[0];

    const float e0 = __expf(v.x - M), e1 = __expf(v.y - M);
    const float e2 = __expf(v.z - M), e3 = __expf(v.w - M);
    sh_e[(n0 + 0) + ((n0 + 0) >> 5)] = e0;
    sh_e[(n0 + 1) + ((n0 + 1) >> 5)] = e1;
    sh_e[(n0 + 2) + ((n0 + 2) >> 5)] = e2;
    sh_e[(n0 + 3) + ((n0 + 3) >> 5)] = e3;
    __syncthreads();

    if (tid < 32) {
        float s = 0.f;
        #pragma unroll
        for (int j = 0; j < 32; j++) s += sh_e[tid * 33 + j];
        iRS[tid] = __fdividef(1.f, s);
    } else if (tid < 64) {
        const int g2 = tid - 32;
        float s = 0.f;
        #pragma unroll
        for (int j = 0; j < 32; j++) s += sh_e[j * 33 + g2];
        iCS[g2] = __fdividef(1.f, s);
    }
    __syncthreads();

    const int g1 = n0 >> 5, g2 = n0 & 31;
    const float irs = iRS[g1];
    const float c0 = e0 * e0 * irs * iCS[g2 + 0];
    const float c1 = e1 * e1 * irs * iCS[g2 + 1];
    const float c2 = e2 * e2 * irs * iCS[g2 + 2];
    const float c3 = e3 * e3 * irs * iCS[g2 + 3];

    float s = c0 + c1 + c2 + c3;
    #pragma unroll
    for (int st = 16; st > 0; st >>= 1)
        s += __shfl_xor_sync(0xffffffffu, s, st);
    if (lane == 0) wred[wp] = s;
    __syncthreads();
    if (tid == 0) {
        float ss = 0.f;
        #pragma unroll
        for (int i = 0; i < 8; i++) ss += wred[i];
        sh_bcast[1] = __fdividef(1.0f, ss + 1e-8f);
    }
    __syncthreads();
    const float inv = sh_bcast[1];

    __half h0 = __float2half_rn(c0 * inv), h1 = __float2half_rn(c1 * inv);
    __half h2 = __float2half_rn(c2 * inv), h3 = __float2half_rn(c3 * inv);
    __half2* ph = reinterpret_cast<__half2*>(Phi + (size_t)b * 1024 + n0);
    ph[0] = __halves2half2(h0, h1); ph[1] = __halves2half2(h2, h3);
}

// ---------------- mma.sync split-fp16 GEMM -----------------------------------
// CTA 128x128, 256 threads = 8 warps (2m x 4n), warp tile 64x32.
// K-stage 64 (128B SW128 rows), 3-stage cp.async pipeline.
// TERMS==2: Ahi*Bhi (f32 acc) + Alo*Bhi (f16 acc).  TERMS==1: Ahi*Bhi only.
// EPI==1:   C = 2*acc - wsq[col].
#define TILE16   16384                 // one 128x64 f16 tile (128 rows x 128B)
#define TSTAGES  16                    // 1024 / 64

template<int EPI, int TERMS>
__global__ __launch_bounds__(256, 1)
void mma_gemm(const __half* __restrict__ Ahi, const __half* __restrict__ Alo,
              const __half* __restrict__ Bhi,
              float* __restrict__ C, const float* __restrict__ wsq)
{
    constexpr bool HAS_CORR = (TERMS == 2);
    constexpr uint32_t NTILES  = HAS_CORR ? 3 : 2;
    constexpr uint32_t STAGE_B = NTILES * TILE16;
    constexpr uint32_t OFF_ALO = TILE16;
    constexpr uint32_t OFF_BHI = (HAS_CORR ? 2 : 1) * TILE16;

    extern __shared__ char dyn[];
    const uint32_t sbase = (s2u(dyn) + 1023u) & ~1023u;

    const int tid  = threadIdx.x;
    const int w    = tid >> 5, lane = tid & 31;
    const int nT   = blockIdx.x, mT = blockIdx.y;
    const int wm   = (w >> 2) * 64;    // 2 warps along m
    const int wn   = (w & 3) * 32;     // 4 warps along n

    // ---- gmem loader geometry: thread covers row tid>>1, 64B half-row ------
    const int lr = tid >> 1;
    const uint32_t lc = (tid & 1) * 64;
    uint32_t lso[4];
    #pragma unroll
    for (int i = 0; i < 4; i++) lso[i] = swz128((uint32_t)lr * 128u + lc + i * 16);

    const char* gAhi = (const char*)Ahi + (size_t)(mT * 128 + lr) * 2048 + lc;
    const char* gAlo = HAS_CORR ? (const char*)Alo + (size_t)(mT * 128 + lr) * 2048 + lc : nullptr;
    const char* gBhi = (const char*)Bhi + (size_t)(nT * 128 + lr) * 2048 + lc;

    auto load_stage = [&](int t, int slot) {
        const uint32_t sb = sbase + (uint32_t)slot * STAGE_B;
        const size_t tb = (size_t)t * 128;   // 64 f16 = 128B along K
        #pragma unroll
        for (int i = 0; i < 4; i++) {
            const size_t go = tb + i * 16;
            cpa16(sb + lso[i], gAhi + go);
            if (HAS_CORR) cpa16(sb + OFF_ALO + lso[i], gAlo + go);
            cpa16(sb + OFF_BHI + lso[i], gBhi + go);
        }
        CP_COMMIT();
    };

    // ---- ldmatrix base addresses (swizzled; k-step folds in via XOR) -------
    uint32_t a0[4];
    {
        const int rsel = (lane >> 4) * 16;
        #pragma unroll
        for (int mi = 0; mi < 4; mi++) {
            const int row = wm + mi * 16 + (lane & 15);
            a0[mi] = (uint32_t)row * 128u + (uint32_t)(rsel ^ ((row & 7) << 4));
        }
    }
    uint32_t b0[2];
    {
        const int selb = ((lane >> 3) & 1) * 16;
        #pragma unroll
        for (int p = 0; p < 2; p++) {
            const int row = wn + p * 16 + ((lane >> 4) << 3) + (lane & 7);
            b0[p] = (uint32_t)row * 128u + (uint32_t)(selb ^ ((row & 7) << 4));
        }
    }

    float d[4][4][4];
    #pragma unroll
    for (int i = 0; i < 4; i++)
        #pragma unroll
        for (int j = 0; j < 4; j++)
            #pragma unroll
            for (int k = 0; k < 4; k++) d[i][j][k] = 0.f;

    uint32_t dc[4][4][2];   // f16 accumulator for the correction term
    if (HAS_CORR) {
        #pragma unroll
        for (int i = 0; i < 4; i++)
            #pragma unroll
            for (int j = 0; j < 4; j++) { dc[i][j][0] = 0u; dc[i][j][1] = 0u; }
    }

    load_stage(0, 0);
    load_stage(1, 1);

    for (int t = 0; t < TSTAGES; t++) {
        if (t + 2 < TSTAGES) {
            load_stage(t + 2, (t + 2) % 3);
            CP_WAIT(2);
        } else if (t + 1 < TSTAGES) {
            CP_WAIT(1);
        } else {
            CP_WAIT(0);
        }
        __syncthreads();

        const uint32_t sb = sbase + (uint32_t)(t % 3) * STAGE_B;
        #pragma unroll
        for (int k16 = 0; k16 < 4; k16++) {
            const uint32_t kb = (uint32_t)k16 * 32;
            uint32_t ah[16], al[16], bh[8];
            #pragma unroll
            for (int mi = 0; mi < 4; mi++) ldsm_x4(&ah[mi * 4], sb + (a0[mi] ^ kb));
            if (HAS_CORR) {
                #pragma unroll
                for (int mi = 0; mi < 4; mi++) ldsm_x4(&al[mi * 4], sb + OFF_ALO + (a0[mi] ^ kb));
            }
            #pragma unroll
            for (int p = 0; p < 2; p++) ldsm_x4(&bh[p * 4], sb + OFF_BHI + (b0[p] ^ kb));
            // main term: f32 accumulators
            #pragma unroll
            for (int mi = 0; mi < 4; mi++)
                #pragma unroll
                for (int nj = 0; nj < 4; nj++)
                    mma16816(d[mi][nj], &ah[mi * 4], &bh[(nj >> 1) * 4 + (nj & 1) * 2]);
            // correction: f16 accumulators
            if (HAS_CORR) {
                #pragma unroll
                for (int mi = 0; mi < 4; mi++)
                    #pragma unroll
                    for (int nj = 0; nj < 4; nj++)
                        mma16816h(dc[mi][nj], &al[mi * 4], &bh[(nj >> 1) * 4 + (nj & 1) * 2]);
            }
        }
        __syncthreads();
    }

    // ---- epilogue -----------------------------------------------------------
    #pragma unroll
    for (int mi = 0; mi < 4; mi++) {
        const int row0 = mT * 128 + wm + mi * 16 + (lane >> 2);
        #pragma unroll
        for (int nj = 0; nj < 4; nj++) {
            const int col = nT * 128 + wn + nj * 8 + (lane & 3) * 2;
            float v0 = d[mi][nj][0], v1 = d[mi][nj][1];
            float v2 = d[mi][nj][2], v3 = d[mi][nj][3];
            if (HAS_CORR) {
                const __half2 c01 = *reinterpret_cast<const __half2*>(&dc[mi][nj][0]);
                const __half2 c23 = *reinterpret_cast<const __half2*>(&dc[mi][nj][1]);
                v0 += __half2float(c01.x); v1 += __half2float(c01.y);
                v2 += __half2float(c23.x); v3 += __half2float(c23.y);
            }
            float2 o0, o1;
            if (EPI == 1) {
                const float w0 = __ldg(&wsq[col]);
                const float w1 = __ldg(&wsq[col + 1]);
                o0.x = 2.f * v0 - w0; o0.y = 2.f * v1 - w1;
                o1.x = 2.f * v2 - w0; o1.y = 2.f * v3 - w1;
            } else {
                o0.x = v0; o0.y = v1;
                o1.x = v2; o1.y = v3;
            }
            *reinterpret_cast<float2*>(C + (size_t)row0 * 1024 + col) = o0;
            *reinterpret_cast<float2*>(C + (size_t)(row0 + 8) * 1024 + col) = o1;
        }
    }
}

// ---------------------------------------------------------------------------
extern "C" void kernel_launch(void* const* d_in, const int* in_sizes, int n_in,
                              void* d_out, int out_size) {
    const float* x = (const float*)d_in[0];   // [16384, 1024]
    const float* w = (const float*)d_in[1];   // [32, 32, 1024] = [1024, 1024]
    float* out = (float*)d_out;               // [16384, 1024]

    float *logits, *wsq;
    __half *xhi, *xlo, *whi, *wthi, *phi;
    cudaGetSymbolAddress((void**)&logits, g_logits);
    cudaGetSymbolAddress((void**)&wsq,    g_wsq);
    cudaGetSymbolAddress((void**)&xhi,    g_xhi);
    cudaGetSymbolAddress((void**)&xlo,    g_xlo);
    cudaGetSymbolAddress((void**)&whi,    g_whi);
    cudaGetSymbolAddress((void**)&wthi,   g_wthi);
    cudaGetSymbolAddress((void**)&phi,    g_phi);

    const int SMEM1 = 3 * 3 * TILE16 + 1024;   // 148480 B
    const int SMEM2 = 3 * 2 * TILE16 + 1024;   //  99328 B
    cudaFuncSetAttribute(mma_gemm<1, 2>, cudaFuncAttributeMaxDynamicSharedMemorySize, SMEM1);
    cudaFuncSetAttribute(mma_gemm<0, 1>, cudaFuncAttributeMaxDynamicSharedMemorySize, SMEM2);

    // prologue conversions
    wsq_kernel<<<NCODE, 256>>>(w, wsq);
    const int xn4 = BROWS * DIM / 4;
    split_kernel<<<(xn4 + 255) / 256, 256>>>(x, xhi, xlo, xn4);
    wprep_kernel<<<dim3(32, 32), dim3(32, 32)>>>(w, whi, wthi);

    // GEMM1: logits = 2*x@W^T - wsq   (2 terms: xhi*whi f32 + xlo*whi f16)
    mma_gemm<1, 2><<<dim3(NCODE / 128, BROWS / 128), 256, SMEM1>>>(
        xhi, xlo, whi, logits, wsq);

    // combine: double softmax + product + normalize -> P (fp16)
    combine_kernel<<<BROWS, 256>>>(logits, phi);

    // GEMM2: out = Phi @ fp16(W)   (1 term; B operand = W^T, K-major)
    mma_gemm<0, 1><<<dim3(DIM / 128, BROWS / 128), 256, SMEM2>>>(
        phi, nullptr, wthi, out, nullptr);
}

// round 12
// speedup vs baseline: 3.2004x; 1.1931x over previous
#include <cuda_runtime.h>
#include <cuda_fp16.h>
#include <math.h>
#include <stdint.h>

// Problem shape (fixed): B=16384 rows, D=1024, grid 32x32 -> N=1024 codes
#define BROWS 16384
#define DIM   1024
#define NCODE 1024

// ---------------- scratch (__device__ globals; allocation-free rule) -------
__device__ float g_logits[(size_t)BROWS * NCODE];    // 64MB
__device__ float g_wsq[NCODE];
__device__ __half g_xhi[(size_t)BROWS * DIM];
__device__ __half g_xlo[(size_t)BROWS * DIM];
__device__ __half g_whi[(size_t)NCODE * DIM];
__device__ __half g_wthi[(size_t)DIM * NCODE];
__device__ __half g_phi[(size_t)BROWS * NCODE];

// ---------------- PTX helpers ----------------------------------------------
__device__ __forceinline__ uint32_t s2u(const void* p) {
    uint32_t a;
    asm("{ .reg .u64 t; cvta.to.shared.u64 t, %1; cvt.u32.u64 %0, t; }" : "=r"(a) : "l"(p));
    return a;
}
__device__ __forceinline__ uint32_t swz128(uint32_t o) { return o ^ ((o >> 3) & 0x70); }

__device__ __forceinline__ void cpa16(uint32_t dst, const void* src) {
    asm volatile("cp.async.cg.shared.global [%0], [%1], 16;" :: "r"(dst), "l"(src));
}
#define CP_COMMIT() asm volatile("cp.async.commit_group;")
#define CP_WAIT(n)  asm volatile("cp.async.wait_group %0;" :: "n"(n))

__device__ __forceinline__ void ldsm_x4(uint32_t* r, uint32_t addr) {
    asm volatile("ldmatrix.sync.aligned.m8n8.x4.shared.b16 {%0,%1,%2,%3}, [%4];"
                 : "=r"(r[0]), "=r"(r[1]), "=r"(r[2]), "=r"(r[3]) : "r"(addr));
}
__device__ __forceinline__ void mma16816(float* d, const uint32_t* a, const uint32_t* b) {
    asm volatile("mma.sync.aligned.m16n8k16.row.col.f32.f16.f16.f32 "
                 "{%0,%1,%2,%3}, {%4,%5,%6,%7}, {%8,%9}, {%0,%1,%2,%3};"
                 : "+f"(d[0]), "+f"(d[1]), "+f"(d[2]), "+f"(d[3])
                 : "r"(a[0]), "r"(a[1]), "r"(a[2]), "r"(a[3]), "r"(b[0]), "r"(b[1]));
}
// f16-accumulator HMMA (for small correction term)
__device__ __forceinline__ void mma16816h(uint32_t* d, const uint32_t* a, const uint32_t* b) {
    asm volatile("mma.sync.aligned.m16n8k16.row.col.f16.f16.f16.f16 "
                 "{%0,%1}, {%2,%3,%4,%5}, {%6,%7}, {%0,%1};"
                 : "+r"(d[0]), "+r"(d[1])
                 : "r"(a[0]), "r"(a[1]), "r"(a[2]), "r"(a[3]), "r"(b[0]), "r"(b[1]));
}

// ---------------- small kernels ---------------------------------------------
__global__ void wsq_kernel(const float* __restrict__ W, float* __restrict__ wsq) {
    const int n = blockIdx.x, tid = threadIdx.x;
    const float4 v = *reinterpret_cast<const float4*>(W + (size_t)n * DIM + tid * 4);
    float s = v.x * v.x + v.y * v.y + v.z * v.z + v.w * v.w;
    __shared__ float red[256];
    red[tid] = s;
    __syncthreads();
    #pragma unroll
    for (int st = 128; st > 0; st >>= 1) {
        if (tid < st) red[tid] += red[tid + st];
        __syncthreads();
    }
    if (tid == 0) wsq[n] = red[0];
}

// hi = f16(v), lo = f16(v - hi). 4 elems/thread. (x only)
__global__ void split_kernel(const float* __restrict__ src,
                             __half* __restrict__ hi, __half* __restrict__ lo, int n4) {
    int i = blockIdx.x * blockDim.x + threadIdx.x;
    if (i >= n4) return;
    float4 v = reinterpret_cast<const float4*>(src)[i];
    __half h0 = __float2half_rn(v.x), h1 = __float2half_rn(v.y);
    __half h2 = __float2half_rn(v.z), h3 = __float2half_rn(v.w);
    __half l0 = __float2half_rn(v.x - __half2float(h0));
    __half l1 = __float2half_rn(v.y - __half2float(h1));
    __half l2 = __float2half_rn(v.z - __half2float(h2));
    __half l3 = __float2half_rn(v.w - __half2float(h3));
    __half2* ph = reinterpret_cast<__half2*>(hi) + 2 * i;
    __half2* pl = reinterpret_cast<__half2*>(lo) + 2 * i;
    ph[0] = __halves2half2(h0, h1); ph[1] = __halves2half2(h2, h3);
    pl[0] = __halves2half2(l0, l1); pl[1] = __halves2half2(l2, l3);
}

// W prep (fused): whi[n][d] = f16(W[n][d]); wthi[d][n] = f16(W[n][d]).
__global__ void wprep_kernel(const float* __restrict__ W,
                             __half* __restrict__ Whi,
                             __half* __restrict__ WThi) {
    __shared__ float tile[32][33];
    const int tx = threadIdx.x, ty = threadIdx.y;
    const int bd = blockIdx.x, bn = blockIdx.y;
    const float v = W[(size_t)(bn * 32 + ty) * DIM + bd * 32 + tx];
    tile[ty][tx] = v;
    Whi[(size_t)(bn * 32 + ty) * DIM + bd * 32 + tx] = __float2half_rn(v);
    __syncthreads();
    WThi[(size_t)(bd * 32 + ty) * NCODE + bn * 32 + tx] = __float2half_rn(tile[tx][ty]);
}

// per-row double softmax + product + normalize; emits fp16 P.
__global__ void combine_kernel(const float* __restrict__ L,
                               __half* __restrict__ Phi) {
    const int b = blockIdx.x, tid = threadIdx.x;
    const int lane = tid & 31, wp = tid >> 5;
    const float* row = L + (size_t)b * 1024;

    __shared__ float sh_e[1024 + 32];  // stride-33 padded
    __shared__ float wred[8];
    __shared__ float iRS[32], iCS[32];
    __shared__ float sh_bcast[2];

    const int n0 = tid * 4;
    float4 v = *reinterpret_cast<const float4*>(row + n0);

    float m = fmaxf(fmaxf(v.x, v.y), fmaxf(v.z, v.w));
    #pragma unroll
    for (int s = 16; s > 0; s >>= 1)
        m = fmaxf(m, __shfl_xor_sync(0xffffffffu, m, s));
    if (lane == 0) wred[wp] = m;
    __syncthreads();
    if (tid == 0) {
        float mm = wred[0];
        #pragma unroll
        for (int i = 1; i < 8; i++) mm = fmaxf(mm, wred[i]);
        sh_bcast[0] = mm;
    }
    __syncthreads();
    const float M = sh_bcast[0];

    const float e0 = __expf(v.x - M), e1 = __expf(v.y - M);
    const float e2 = __expf(v.z - M), e3 = __expf(v.w - M);
    sh_e[(n0 + 0) + ((n0 + 0) >> 5)] = e0;
    sh_e[(n0 + 1) + ((n0 + 1) >> 5)] = e1;
    sh_e[(n0 + 2) + ((n0 + 2) >> 5)] = e2;
    sh_e[(n0 + 3) + ((n0 + 3) >> 5)] = e3;
    __syncthreads();

    if (tid < 32) {
        float s = 0.f;
        #pragma unroll
        for (int j = 0; j < 32; j++) s += sh_e[tid * 33 + j];
        iRS[tid] = __fdividef(1.f, s);
    } else if (tid < 64) {
        const int g2 = tid - 32;
        float s = 0.f;
        #pragma unroll
        for (int j = 0; j < 32; j++) s += sh_e[j * 33 + g2];
        iCS[g2] = __fdividef(1.f, s);
    }
    __syncthreads();

    const int g1 = n0 >> 5, g2 = n0 & 31;
    const float irs = iRS[g1];
    const float c0 = e0 * e0 * irs * iCS[g2 + 0];
    const float c1 = e1 * e1 * irs * iCS[g2 + 1];
    const float c2 = e2 * e2 * irs * iCS[g2 + 2];
    const float c3 = e3 * e3 * irs * iCS[g2 + 3];

    float s = c0 + c1 + c2 + c3;
    #pragma unroll
    for (int st = 16; st > 0; st >>= 1)
        s += __shfl_xor_sync(0xffffffffu, s, st);
    if (lane == 0) wred[wp] = s;
    __syncthreads();
    if (tid == 0) {
        float ss = 0.f;
        #pragma unroll
        for (int i = 0; i < 8; i++) ss += wred[i];
        sh_bcast[1] = __fdividef(1.0f, ss + 1e-8f);
    }
    __syncthreads();
    const float inv = sh_bcast[1];

    __half h0 = __float2half_rn(c0 * inv), h1 = __float2half_rn(c1 * inv);
    __half h2 = __float2half_rn(c2 * inv), h3 = __float2half_rn(c3 * inv);
    __half2* ph = reinterpret_cast<__half2*>(Phi + (size_t)b * 1024 + n0);
    ph[0] = __halves2half2(h0, h1); ph[1] = __halves2half2(h2, h3);
}

// ---------------- mma.sync split-fp16 GEMM -----------------------------------
// CTA 128x128, 512 threads = 16 warps (4m x 4n), warp tile 32x32.
// 4 warps/SMSP for latency hiding (R11 ncu: tensor=47.5% at 2 warps/SMSP).
// K-stage 64 (128B SW128 rows), 3-stage cp.async pipeline.
// TERMS==2: Ahi*Bhi (f32 acc) + Alo*Bhi (f16 acc).  TERMS==1: Ahi*Bhi only.
// EPI==1:   C = 2*acc - wsq[col].
#define TILE16   16384                 // one 128x64 f16 tile (128 rows x 128B)
#define TSTAGES  16                    // 1024 / 64

template<int EPI, int TERMS>
__global__ __launch_bounds__(512, 1)
void mma_gemm(const __half* __restrict__ Ahi, const __half* __restrict__ Alo,
              const __half* __restrict__ Bhi,
              float* __restrict__ C, const float* __restrict__ wsq)
{
    constexpr bool HAS_CORR = (TERMS == 2);
    constexpr uint32_t NTILES  = HAS_CORR ? 3 : 2;
    constexpr uint32_t STAGE_B = NTILES * TILE16;
    constexpr uint32_t OFF_ALO = TILE16;
    constexpr uint32_t OFF_BHI = (HAS_CORR ? 2 : 1) * TILE16;

    extern __shared__ char dyn[];
    const uint32_t sbase = (s2u(dyn) + 1023u) & ~1023u;

    const int tid  = threadIdx.x;
    const int w    = tid >> 5, lane = tid & 31;
    const int nT   = blockIdx.x, mT = blockIdx.y;
    const int wm   = (w >> 2) * 32;    // 4 warps along m
    const int wn   = (w & 3) * 32;     // 4 warps along n

    // ---- gmem loader geometry: thread covers row tid>>2, 32B quarter-row ---
    const int lr = tid >> 2;
    const uint32_t lc = (tid & 3) * 32;
    uint32_t lso[2];
    #pragma unroll
    for (int i = 0; i < 2; i++) lso[i] = swz128((uint32_t)lr * 128u + lc + i * 16);

    const char* gAhi = (const char*)Ahi + (size_t)(mT * 128 + lr) * 2048 + lc;
    const char* gAlo = HAS_CORR ? (const char*)Alo + (size_t)(mT * 128 + lr) * 2048 + lc : nullptr;
    const char* gBhi = (const char*)Bhi + (size_t)(nT * 128 + lr) * 2048 + lc;

    auto load_stage = [&](int t, int slot) {
        const uint32_t sb = sbase + (uint32_t)slot * STAGE_B;
        const size_t tb = (size_t)t * 128;   // 64 f16 = 128B along K
        #pragma unroll
        for (int i = 0; i < 2; i++) {
            const size_t go = tb + i * 16;
            cpa16(sb + lso[i], gAhi + go);
            if (HAS_CORR) cpa16(sb + OFF_ALO + lso[i], gAlo + go);
            cpa16(sb + OFF_BHI + lso[i], gBhi + go);
        }
        CP_COMMIT();
    };

    // ---- ldmatrix base addresses (swizzled; k-step folds in via XOR) -------
    uint32_t a0[2];
    {
        const int rsel = (lane >> 4) * 16;
        #pragma unroll
        for (int mi = 0; mi < 2; mi++) {
            const int row = wm + mi * 16 + (lane & 15);
            a0[mi] = (uint32_t)row * 128u + (uint32_t)(rsel ^ ((row & 7) << 4));
        }
    }
    uint32_t b0[2];
    {
        const int selb = ((lane >> 3) & 1) * 16;
        #pragma unroll
        for (int p = 0; p < 2; p++) {
            const int row = wn + p * 16 + ((lane >> 4) << 3) + (lane & 7);
            b0[p] = (uint32_t)row * 128u + (uint32_t)(selb ^ ((row & 7) << 4));
        }
    }

    float d[2][4][4];
    #pragma unroll
    for (int i = 0; i < 2; i++)
        #pragma unroll
        for (int j = 0; j < 4; j++)
            #pragma unroll
            for (int k = 0; k < 4; k++) d[i][j][k] = 0.f;

    uint32_t dc[2][4][2];   // f16 accumulator for the correction term
    if (HAS_CORR) {
        #pragma unroll
        for (int i = 0; i < 2; i++)
            #pragma unroll
            for (int j = 0; j < 4; j++) { dc[i][j][0] = 0u; dc[i][j][1] = 0u; }
    }

    load_stage(0, 0);
    load_stage(1, 1);

    for (int t = 0; t < TSTAGES; t++) {
        if (t + 2 < TSTAGES) {
            load_stage(t + 2, (t + 2) % 3);
            CP_WAIT(2);
        } else if (t + 1 < TSTAGES) {
            CP_WAIT(1);
        } else {
            CP_WAIT(0);
        }
        __syncthreads();

        const uint32_t sb = sbase + (uint32_t)(t % 3) * STAGE_B;
        #pragma unroll
        for (int k16 = 0; k16 < 4; k16++) {
            const uint32_t kb = (uint32_t)k16 * 32;
            uint32_t ah[8], al[8], bh[8];
            #pragma unroll
            for (int mi = 0; mi < 2; mi++) ldsm_x4(&ah[mi * 4], sb + (a0[mi] ^ kb));
            if (HAS_CORR) {
                #pragma unroll
                for (int mi = 0; mi < 2; mi++) ldsm_x4(&al[mi * 4], sb + OFF_ALO + (a0[mi] ^ kb));
            }
            #pragma unroll
            for (int p = 0; p < 2; p++) ldsm_x4(&bh[p * 4], sb + OFF_BHI + (b0[p] ^ kb));
            // main term: f32 accumulators
            #pragma unroll
            for (int mi = 0; mi < 2; mi++)
                #pragma unroll
                for (int nj = 0; nj < 4; nj++)
                    mma16816(d[mi][nj], &ah[mi * 4], &bh[(nj >> 1) * 4 + (nj & 1) * 2]);
            // correction: f16 accumulators
            if (HAS_CORR) {
                #pragma unroll
                for (int mi = 0; mi < 2; mi++)
                    #pragma unroll
                    for (int nj = 0; nj < 4; nj++)
                        mma16816h(dc[mi][nj], &al[mi * 4], &bh[(nj >> 1) * 4 + (nj & 1) * 2]);
            }
        }
        __syncthreads();
    }

    // ---- epilogue -----------------------------------------------------------
    #pragma unroll
    for (int mi = 0; mi < 2; mi++) {
        const int row0 = mT * 128 + wm + mi * 16 + (lane >> 2);
        #pragma unroll
        for (int nj = 0; nj < 4; nj++) {
            const int col = nT * 128 + wn + nj * 8 + (lane & 3) * 2;
            float v0 = d[mi][nj][0], v1 = d[mi][nj][1];
            float v2 = d[mi][nj][2], v3 = d[mi][nj][3];
            if (HAS_CORR) {
                const __half2 c01 = *reinterpret_cast<const __half2*>(&dc[mi][nj][0]);
                const __half2 c23 = *reinterpret_cast<const __half2*>(&dc[mi][nj][1]);
                v0 += __half2float(c01.x); v1 += __half2float(c01.y);
                v2 += __half2float(c23.x); v3 += __half2float(c23.y);
            }
            float2 o0, o1;
            if (EPI == 1) {
                const float w0 = __ldg(&wsq[col]);
                const float w1 = __ldg(&wsq[col + 1]);
                o0.x = 2.f * v0 - w0; o0.y = 2.f * v1 - w1;
                o1.x = 2.f * v2 - w0; o1.y = 2.f * v3 - w1;
            } else {
                o0.x = v0; o0.y = v1;
                o1.x = v2; o1.y = v3;
            }
            *reinterpret_cast<float2*>(C + (size_t)row0 * 1024 + col) = o0;
            *reinterpret_cast<float2*>(C + (size_t)(row0 + 8) * 1024 + col) = o1;
        }
    }
}

// ---------------------------------------------------------------------------
extern "C" void kernel_launch(void* const* d_in, const int* in_sizes, int n_in,
                              void* d_out, int out_size) {
    const float* x = (const float*)d_in[0];   // [16384, 1024]
    const float* w = (const float*)d_in[1];   // [32, 32, 1024] = [1024, 1024]
    float* out = (float*)d_out;               // [16384, 1024]

    float *logits, *wsq;
    __half *xhi, *xlo, *whi, *wthi, *phi;
    cudaGetSymbolAddress((void**)&logits, g_logits);
    cudaGetSymbolAddress((void**)&wsq,    g_wsq);
    cudaGetSymbolAddress((void**)&xhi,    g_xhi);
    cudaGetSymbolAddress((void**)&xlo,    g_xlo);
    cudaGetSymbolAddress((void**)&whi,    g_whi);
    cudaGetSymbolAddress((void**)&wthi,   g_wthi);
    cudaGetSymbolAddress((void**)&phi,    g_phi);

    const int SMEM1 = 3 * 3 * TILE16 + 1024;   // 148480 B
    const int SMEM2 = 3 * 2 * TILE16 + 1024;   //  99328 B
    cudaFuncSetAttribute(mma_gemm<1, 2>, cudaFuncAttributeMaxDynamicSharedMemorySize, SMEM1);
    cudaFuncSetAttribute(mma_gemm<0, 1>, cudaFuncAttributeMaxDynamicSharedMemorySize, SMEM2);

    // prologue conversions
    wsq_kernel<<<NCODE, 256>>>(w, wsq);
    const int xn4 = BROWS * DIM / 4;
    split_kernel<<<(xn4 + 255) / 256, 256>>>(x, xhi, xlo, xn4);
    wprep_kernel<<<dim3(32, 32), dim3(32, 32)>>>(w, whi, wthi);

    // GEMM1: logits = 2*x@W^T - wsq   (2 terms: xhi*whi f32 + xlo*whi f16)
    mma_gemm<1, 2><<<dim3(NCODE / 128, BROWS / 128), 512, SMEM1>>>(
        xhi, xlo, whi, logits, wsq);

    // combine: double softmax + product + normalize -> P (fp16)
    combine_kernel<<<BROWS, 256>>>(logits, phi);

    // GEMM2: out = Phi @ fp16(W)   (1 term; B operand = W^T, K-major)
    mma_gemm<0, 1><<<dim3(DIM / 128, BROWS / 128), 512, SMEM2>>>(
        phi, nullptr, wthi, out, nullptr);
}

// round 13
// speedup vs baseline: 3.4477x; 1.0773x over previous
#include <cuda_runtime.h>
#include <cuda_fp16.h>
#include <math.h>
#include <stdint.h>

// Problem shape (fixed): B=16384 rows, D=1024, grid 32x32 -> N=1024 codes
#define BROWS 16384
#define DIM   1024
#define NCODE 1024

// ---------------- scratch (__device__ globals; allocation-free rule) -------
__device__ float g_logits[(size_t)BROWS * NCODE];    // 64MB
__device__ float g_wsq[NCODE];
__device__ __half g_xhi[(size_t)BROWS * DIM];
__device__ __half g_xlo[(size_t)BROWS * DIM];
__device__ __half g_whi[(size_t)NCODE * DIM];
__device__ __half g_wthi[(size_t)DIM * NCODE];
__device__ __half g_phi[(size_t)BROWS * NCODE];

// ---------------- PTX helpers ----------------------------------------------
__device__ __forceinline__ uint32_t s2u(const void* p) {
    uint32_t a;
    asm("{ .reg .u64 t; cvta.to.shared.u64 t, %1; cvt.u32.u64 %0, t; }" : "=r"(a) : "l"(p));
    return a;
}
__device__ __forceinline__ uint32_t swz128(uint32_t o) { return o ^ ((o >> 3) & 0x70); }

__device__ __forceinline__ void cpa16(uint32_t dst, const void* src) {
    asm volatile("cp.async.cg.shared.global [%0], [%1], 16;" :: "r"(dst), "l"(src));
}
#define CP_COMMIT() asm volatile("cp.async.commit_group;")
#define CP_WAIT(n)  asm volatile("cp.async.wait_group %0;" :: "n"(n))

__device__ __forceinline__ void ldsm_x4(uint32_t* r, uint32_t addr) {
    asm volatile("ldmatrix.sync.aligned.m8n8.x4.shared.b16 {%0,%1,%2,%3}, [%4];"
                 : "=r"(r[0]), "=r"(r[1]), "=r"(r[2]), "=r"(r[3]) : "r"(addr));
}
__device__ __forceinline__ void mma16816(float* d, const uint32_t* a, const uint32_t* b) {
    asm volatile("mma.sync.aligned.m16n8k16.row.col.f32.f16.f16.f32 "
                 "{%0,%1,%2,%3}, {%4,%5,%6,%7}, {%8,%9}, {%0,%1,%2,%3};"
                 : "+f"(d[0]), "+f"(d[1]), "+f"(d[2]), "+f"(d[3])
                 : "r"(a[0]), "r"(a[1]), "r"(a[2]), "r"(a[3]), "r"(b[0]), "r"(b[1]));
}
// f16-accumulator HMMA (for small correction term)
__device__ __forceinline__ void mma16816h(uint32_t* d, const uint32_t* a, const uint32_t* b) {
    asm volatile("mma.sync.aligned.m16n8k16.row.col.f16.f16.f16.f16 "
                 "{%0,%1}, {%2,%3,%4,%5}, {%6,%7}, {%0,%1};"
                 : "+r"(d[0]), "+r"(d[1])
                 : "r"(a[0]), "r"(a[1]), "r"(a[2]), "r"(a[3]), "r"(b[0]), "r"(b[1]));
}

// ---------------- small kernels ---------------------------------------------
__global__ void wsq_kernel(const float* __restrict__ W, float* __restrict__ wsq) {
    const int n = blockIdx.x, tid = threadIdx.x;
    const float4 v = *reinterpret_cast<const float4*>(W + (size_t)n * DIM + tid * 4);
    float s = v.x * v.x + v.y * v.y + v.z * v.z + v.w * v.w;
    __shared__ float red[256];
    red[tid] = s;
    __syncthreads();
    #pragma unroll
    for (int st = 128; st > 0; st >>= 1) {
        if (tid < st) red[tid] += red[tid + st];
        __syncthreads();
    }
    if (tid == 0) wsq[n] = red[0];
}

// hi = f16(v), lo = f16(v - hi). 4 elems/thread. (x only)
__global__ void split_kernel(const float* __restrict__ src,
                             __half* __restrict__ hi, __half* __restrict__ lo, int n4) {
    int i = blockIdx.x * blockDim.x + threadIdx.x;
    if (i >= n4) return;
    float4 v = reinterpret_cast<const float4*>(src)[i];
    __half h0 = __float2half_rn(v.x), h1 = __float2half_rn(v.y);
    __half h2 = __float2half_rn(v.z), h3 = __float2half_rn(v.w);
    __half l0 = __float2half_rn(v.x - __half2float(h0));
    __half l1 = __float2half_rn(v.y - __half2float(h1));
    __half l2 = __float2half_rn(v.z - __half2float(h2));
    __half l3 = __float2half_rn(v.w - __half2float(h3));
    __half2* ph = reinterpret_cast<__half2*>(hi) + 2 * i;
    __half2* pl = reinterpret_cast<__half2*>(lo) + 2 * i;
    ph[0] = __halves2half2(h0, h1); ph[1] = __halves2half2(h2, h3);
    pl[0] = __halves2half2(l0, l1); pl[1] = __halves2half2(l2, l3);
}

// W prep (fused): whi[n][d] = f16(W[n][d]); wthi[d][n] = f16(W[n][d]).
__global__ void wprep_kernel(const float* __restrict__ W,
                             __half* __restrict__ Whi,
                             __half* __restrict__ WThi) {
    __shared__ float tile[32][33];
    const int tx = threadIdx.x, ty = threadIdx.y;
    const int bd = blockIdx.x, bn = blockIdx.y;
    const float v = W[(size_t)(bn * 32 + ty) * DIM + bd * 32 + tx];
    tile[ty][tx] = v;
    Whi[(size_t)(bn * 32 + ty) * DIM + bd * 32 + tx] = __float2half_rn(v);
    __syncthreads();
    WThi[(size_t)(bd * 32 + ty) * NCODE + bn * 32 + tx] = __float2half_rn(tile[tx][ty]);
}

// per-row double softmax + product + normalize; emits fp16 P.
__global__ void combine_kernel(const float* __restrict__ L,
                               __half* __restrict__ Phi) {
    const int b = blockIdx.x, tid = threadIdx.x;
    const int lane = tid & 31, wp = tid >> 5;
    const float* row = L + (size_t)b * 1024;

    __shared__ float sh_e[1024 + 32];  // stride-33 padded
    __shared__ float wred[8];
    __shared__ float iRS[32], iCS[32];
    __shared__ float sh_bcast[2];

    const int n0 = tid * 4;
    float4 v = *reinterpret_cast<const float4*>(row + n0);

    float m = fmaxf(fmaxf(v.x, v.y), fmaxf(v.z, v.w));
    #pragma unroll
    for (int s = 16; s > 0; s >>= 1)
        m = fmaxf(m, __shfl_xor_sync(0xffffffffu, m, s));
    if (lane == 0) wred[wp] = m;
    __syncthreads();
    if (tid == 0) {
        float mm = wred[0];
        #pragma unroll
        for (int i = 1; i < 8; i++) mm = fmaxf(mm, wred[i]);
        sh_bcast[0] = mm;
    }
    __syncthreads();
    const float M = sh_bcast[0];

    const float e0 = __expf(v.x - M), e1 = __expf(v.y - M);
    const float e2 = __expf(v.z - M), e3 = __expf(v.w - M);
    sh_e[(n0 + 0) + ((n0 + 0) >> 5)] = e0;
    sh_e[(n0 + 1) + ((n0 + 1) >> 5)] = e1;
    sh_e[(n0 + 2) + ((n0 + 2) >> 5)] = e2;
    sh_e[(n0 + 3) + ((n0 + 3) >> 5)] = e3;
    __syncthreads();

    if (tid < 32) {
        float s = 0.f;
        #pragma unroll
        for (int j = 0; j < 32; j++) s += sh_e[tid * 33 + j];
        iRS[tid] = __fdividef(1.f, s);
    } else if (tid < 64) {
        const int g2 = tid - 32;
        float s = 0.f;
        #pragma unroll
        for (int j = 0; j < 32; j++) s += sh_e[j * 33 + g2];
        iCS[g2] = __fdividef(1.f, s);
    }
    __syncthreads();

    const int g1 = n0 >> 5, g2 = n0 & 31;
    const float irs = iRS[g1];
    const float c0 = e0 * e0 * irs * iCS[g2 + 0];
    const float c1 = e1 * e1 * irs * iCS[g2 + 1];
    const float c2 = e2 * e2 * irs * iCS[g2 + 2];
    const float c3 = e3 * e3 * irs * iCS[g2 + 3];

    float s = c0 + c1 + c2 + c3;
    #pragma unroll
    for (int st = 16; st > 0; st >>= 1)
        s += __shfl_xor_sync(0xffffffffu, s, st);
    if (lane == 0) wred[wp] = s;
    __syncthreads();
    if (tid == 0) {
        float ss = 0.f;
        #pragma unroll
        for (int i = 0; i < 8; i++) ss += wred[i];
        sh_bcast[1] = __fdividef(1.0f, ss + 1e-8f);
    }
    __syncthreads();
    const float inv = sh_bcast[1];

    __half h0 = __float2half_rn(c0 * inv), h1 = __float2half_rn(c1 * inv);
    __half h2 = __float2half_rn(c2 * inv), h3 = __float2half_rn(c3 * inv);
    __half2* ph = reinterpret_cast<__half2*>(Phi + (size_t)b * 1024 + n0);
    ph[0] = __halves2half2(h0, h1); ph[1] = __halves2half2(h2, h3);
}

// ---------------- mma.sync split-fp16 GEMM -----------------------------------
// CTA 128x128, 512 threads = 16 warps (4m x 4n), warp tile 32x32.
// K-stage 64 (128B SW128 rows), 3-stage cp.async pipeline, ONE barrier/stage.
// Register fragment pipeline: ah/bh double-buffered across k16; al (corr term)
// reuses the spent ah buffer after the f32 MMAs consume it.
// TERMS==2: Ahi*Bhi (f32 acc) + Alo*Bhi (f16 acc).  TERMS==1: Ahi*Bhi only.
// EPI==1:   C = 2*acc - wsq[col].
#define TILE16   16384                 // one 128x64 f16 tile (128 rows x 128B)
#define TSTAGES  16                    // 1024 / 64

template<int EPI, int TERMS>
__global__ __launch_bounds__(512, 1)
void mma_gemm(const __half* __restrict__ Ahi, const __half* __restrict__ Alo,
              const __half* __restrict__ Bhi,
              float* __restrict__ C, const float* __restrict__ wsq)
{
    constexpr bool HAS_CORR = (TERMS == 2);
    constexpr uint32_t NTILES  = HAS_CORR ? 3 : 2;
    constexpr uint32_t STAGE_B = NTILES * TILE16;
    constexpr uint32_t OFF_ALO = TILE16;
    constexpr uint32_t OFF_BHI = (HAS_CORR ? 2 : 1) * TILE16;

    extern __shared__ char dyn[];
    const uint32_t sbase = (s2u(dyn) + 1023u) & ~1023u;

    const int tid  = threadIdx.x;
    const int w    = tid >> 5, lane = tid & 31;
    const int nT   = blockIdx.x, mT = blockIdx.y;
    const int wm   = (w >> 2) * 32;    // 4 warps along m
    const int wn   = (w & 3) * 32;     // 4 warps along n

    // ---- gmem loader geometry: thread covers row tid>>2, 32B quarter-row ---
    const int lr = tid >> 2;
    const uint32_t lc = (tid & 3) * 32;
    const uint32_t lso0 = swz128((uint32_t)lr * 128u + lc);
    const uint32_t lso1 = swz128((uint32_t)lr * 128u + lc + 16);

    const char* gAhi = (const char*)Ahi + (size_t)(mT * 128 + lr) * 2048 + lc;
    const char* gAlo = HAS_CORR ? (const char*)Alo + (size_t)(mT * 128 + lr) * 2048 + lc : nullptr;
    const char* gBhi = (const char*)Bhi + (size_t)(nT * 128 + lr) * 2048 + lc;

    auto load_stage = [&](int t, int slot) {
        const uint32_t sb = sbase + (uint32_t)slot * STAGE_B;
        const size_t tb = (size_t)t * 128;   // 64 f16 = 128B along K
        cpa16(sb + lso0, gAhi + tb);
        cpa16(sb + lso1, gAhi + tb + 16);
        if (HAS_CORR) {
            cpa16(sb + OFF_ALO + lso0, gAlo + tb);
            cpa16(sb + OFF_ALO + lso1, gAlo + tb + 16);
        }
        cpa16(sb + OFF_BHI + lso0, gBhi + tb);
        cpa16(sb + OFF_BHI + lso1, gBhi + tb + 16);
        CP_COMMIT();
    };

    // ---- ldmatrix base addresses (swizzled; k-step folds in via XOR) -------
    uint32_t a0[2];
    {
        const int rsel = (lane >> 4) * 16;
        #pragma unroll
        for (int mi = 0; mi < 2; mi++) {
            const int row = wm + mi * 16 + (lane & 15);
            a0[mi] = (uint32_t)row * 128u + (uint32_t)(rsel ^ ((row & 7) << 4));
        }
    }
    uint32_t b0[2];
    {
        const int selb = ((lane >> 3) & 1) * 16;
        #pragma unroll
        for (int p = 0; p < 2; p++) {
            const int row = wn + p * 16 + ((lane >> 4) << 3) + (lane & 7);
            b0[p] = (uint32_t)row * 128u + (uint32_t)(selb ^ ((row & 7) << 4));
        }
    }

    float d[2][4][4];
    #pragma unroll
    for (int i = 0; i < 2; i++)
        #pragma unroll
        for (int j = 0; j < 4; j++)
            #pragma unroll
            for (int k = 0; k < 4; k++) d[i][j][k] = 0.f;

    uint32_t dc[2][4][2];   // f16 accumulator for the correction term
    if (HAS_CORR) {
        #pragma unroll
        for (int i = 0; i < 2; i++)
            #pragma unroll
            for (int j = 0; j < 4; j++) { dc[i][j][0] = 0u; dc[i][j][1] = 0u; }
    }

    // prologue: stages 0,1 in flight; stage 0 complete before first compute
    load_stage(0, 0);
    load_stage(1, 1);
    CP_WAIT(1);
    __syncthreads();

    uint32_t ah[2][8], bh[2][8];

    for (int t = 0; t < TSTAGES; t++) {
        const uint32_t sb = sbase + (uint32_t)(t % 3) * STAGE_B;

        // stage-entry fragment load (k16 = 0) into buffer 0
        #pragma unroll
        for (int mi = 0; mi < 2; mi++) ldsm_x4(&ah[0][mi * 4], sb + a0[mi]);
        #pragma unroll
        for (int p = 0; p < 2; p++) ldsm_x4(&bh[0][p * 4], sb + OFF_BHI + b0[p]);

        #pragma unroll
        for (int k16 = 0; k16 < 4; k16++) {
            const int c = k16 & 1, nx = c ^ 1;
            // prefetch next k16 fragments into the alternate buffer
            if (k16 < 3) {
                const uint32_t kb = (uint32_t)(k16 + 1) * 32;
                #pragma unroll
                for (int mi = 0; mi < 2; mi++) ldsm_x4(&ah[nx][mi * 4], sb + (a0[mi] ^ kb));
                #pragma unroll
                for (int p = 0; p < 2; p++) ldsm_x4(&bh[nx][p * 4], sb + OFF_BHI + (b0[p] ^ kb));
            }
            // main term: f32 accumulators (consumes ah[c])
            #pragma unroll
            for (int mi = 0; mi < 2; mi++)
                #pragma unroll
                for (int nj = 0; nj < 4; nj++)
                    mma16816(d[mi][nj], &ah[c][mi * 4], &bh[c][(nj >> 1) * 4 + (nj & 1) * 2]);
            // correction: al loads into the spent ah[c] buffer; latency hides
            // behind the 8 f32 MMAs draining in the tensor queue.
            if (HAS_CORR) {
                const uint32_t kb = (uint32_t)k16 * 32;
                #pragma unroll
                for (int mi = 0; mi < 2; mi++) ldsm_x4(&ah[c][mi * 4], sb + OFF_ALO + (a0[mi] ^ kb));
                #pragma unroll
                for (int mi = 0; mi < 2; mi++)
                    #pragma unroll
                    for (int nj = 0; nj < 4; nj++)
                        mma16816h(dc[mi][nj], &ah[c][mi * 4], &bh[c][(nj >> 1) * 4 + (nj & 1) * 2]);
            }
        }

        // issue next stage load, then ensure stage t+1 is resident; one barrier
        if (t + 2 < TSTAGES) {
            load_stage(t + 2, (t + 2) % 3);
            CP_WAIT(1);
        } else {
            CP_WAIT(0);
        }
        __syncthreads();
    }

    // ---- epilogue -----------------------------------------------------------
    #pragma unroll
    for (int mi = 0; mi < 2; mi++) {
        const int row0 = mT * 128 + wm + mi * 16 + (lane >> 2);
        #pragma unroll
        for (int nj = 0; nj < 4; nj++) {
            const int col = nT * 128 + wn + nj * 8 + (lane & 3) * 2;
            float v0 = d[mi][nj][0], v1 = d[mi][nj][1];
            float v2 = d[mi][nj][2], v3 = d[mi][nj][3];
            if (HAS_CORR) {
                const __half2 c01 = *reinterpret_cast<const __half2*>(&dc[mi][nj][0]);
                const __half2 c23 = *reinterpret_cast<const __half2*>(&dc[mi][nj][1]);
                v0 += __half2float(c01.x); v1 += __half2float(c01.y);
                v2 += __half2float(c23.x); v3 += __half2float(c23.y);
            }
            float2 o0, o1;
            if (EPI == 1) {
                const float w0 = __ldg(&wsq[col]);
                const float w1 = __ldg(&wsq[col + 1]);
                o0.x = 2.f * v0 - w0; o0.y = 2.f * v1 - w1;
                o1.x = 2.f * v2 - w0; o1.y = 2.f * v3 - w1;
            } else {
                o0.x = v0; o0.y = v1;
                o1.x = v2; o1.y = v3;
            }
            *reinterpret_cast<float2*>(C + (size_t)row0 * 1024 + col) = o0;
            *reinterpret_cast<float2*>(C + (size_t)(row0 + 8) * 1024 + col) = o1;
        }
    }
}

// ---------------------------------------------------------------------------
extern "C" void kernel_launch(void* const* d_in, const int* in_sizes, int n_in,
                              void* d_out, int out_size) {
    const float* x = (const float*)d_in[0];   // [16384, 1024]
    const float* w = (const float*)d_in[1];   // [32, 32, 1024] = [1024, 1024]
    float* out = (float*)d_out;               // [16384, 1024]

    float *logits, *wsq;
    __half *xhi, *xlo, *whi, *wthi, *phi;
    cudaGetSymbolAddress((void**)&logits, g_logits);
    cudaGetSymbolAddress((void**)&wsq,    g_wsq);
    cudaGetSymbolAddress((void**)&xhi,    g_xhi);
    cudaGetSymbolAddress((void**)&xlo,    g_xlo);
    cudaGetSymbolAddress((void**)&whi,    g_whi);
    cudaGetSymbolAddress((void**)&wthi,   g_wthi);
    cudaGetSymbolAddress((void**)&phi,    g_phi);

    const int SMEM1 = 3 * 3 * TILE16 + 1024;   // 148480 B
    const int SMEM2 = 3 * 2 * TILE16 + 1024;   //  99328 B
    cudaFuncSetAttribute(mma_gemm<1, 2>, cudaFuncAttributeMaxDynamicSharedMemorySize, SMEM1);
    cudaFuncSetAttribute(mma_gemm<0, 1>, cudaFuncAttributeMaxDynamicSharedMemorySize, SMEM2);

    // prologue conversions
    wsq_kernel<<<NCODE, 256>>>(w, wsq);
    const int xn4 = BROWS * DIM / 4;
    split_kernel<<<(xn4 + 255) / 256, 256>>>(x, xhi, xlo, xn4);
    wprep_kernel<<<dim3(32, 32), dim3(32, 32)>>>(w, whi, wthi);

    // GEMM1: logits = 2*x@W^T - wsq   (2 terms: xhi*whi f32 + xlo*whi f16)
    mma_gemm<1, 2><<<dim3(NCODE / 128, BROWS / 128), 512, SMEM1>>>(
        xhi, xlo, whi, logits, wsq);

    // combine: double softmax + product + normalize -> P (fp16)
    combine_kernel<<<BROWS, 256>>>(logits, phi);

    // GEMM2: out = Phi @ fp16(W)   (1 term; B operand = W^T, K-major)
    mma_gemm<0, 1><<<dim3(DIM / 128, BROWS / 128), 512, SMEM2>>>(
        phi, nullptr, wthi, out, nullptr);
}